// round 14
// baseline (speedup 1.0000x reference)
#include <cuda_runtime.h>
#include <cuda_fp16.h>
#include <math.h>
#include <stdint.h>

// ---- problem constants ----
#define NTOK 844      // B*T = 2*422
#define TSEQ 422
#define BSZ  2
#define CDIM 768
#define NH   32
#define HSD  24
#define NE   32
#define F4D  3072
#define NL   2
#define NV   100

typedef __half fp16;

// ---- device scratch ----
__device__ float g_x  [NTOK * CDIM];
__device__ float g_h  [NTOK * CDIM];
__device__ float g_qkv[NTOK * 3 * CDIM];
__device__ float g_gates[NTOK * NE];
__device__ float g_gwT[NE * CDIM];

__device__ fp16 g_eo [(size_t)NTOK * NE * CDIM];
__device__ fp16 g_hh [NTOK * CDIM];
__device__ fp16 g_atth[NTOK * CDIM];
__device__ fp16 g_wpth[3 * CDIM * CDIM], g_wptl[3 * CDIM * CDIM];
__device__ fp16 g_woth[NL * CDIM * CDIM], g_wotl[NL * CDIM * CDIM];
__device__ fp16 g_w1th[(size_t)NL * NE * F4D * CDIM];
__device__ fp16 g_w2th[(size_t)NL * NE * CDIM * F4D];
__device__ fp16 g_hidh[(size_t)NTOK * NE * F4D];

// ======================= helpers =======================
__device__ __forceinline__ float gelu_exact(float v) {
    return 0.5f * v * (1.f + erff(v * 0.70710678118654752f));
}

__device__ __forceinline__ void mma16816(float* d, const unsigned* a, const unsigned* b) {
    asm volatile(
        "mma.sync.aligned.m16n8k16.row.col.f32.f16.f16.f32 "
        "{%0,%1,%2,%3}, {%4,%5,%6,%7}, {%8,%9}, {%0,%1,%2,%3};"
        : "+f"(d[0]), "+f"(d[1]), "+f"(d[2]), "+f"(d[3])
        : "r"(a[0]), "r"(a[1]), "r"(a[2]), "r"(a[3]), "r"(b[0]), "r"(b[1]));
}

__device__ __forceinline__ void cpa16(unsigned s, const void* g, int sz) {
    asm volatile("cp.async.cg.shared.global [%0], [%1], 16, %2;"
                 :: "r"(s), "l"(g), "r"(sz));
}
#define CPA_COMMIT() asm volatile("cp.async.commit_group;" ::: "memory")
#define CPA_WAIT(n)  asm volatile("cp.async.wait_group %0;" :: "n"(n) : "memory")

#define LDSM4(r0, r1, r2, r3, addr)                                            \
    asm volatile("ldmatrix.sync.aligned.m8n8.x4.shared.b16 {%0,%1,%2,%3}, [%4];" \
        : "=r"(r0), "=r"(r1), "=r"(r2), "=r"(r3) : "r"(addr))

// ======================= shared GEMM geometry =======================
#define STR64 72
#define PL64 (128 * 144)
#define SMEM_3PL 110592            // attn NT2: 2 stages * 3 planes

// ======================= NT2 attention GEMM (A hi; B hi+lo; K-chunk 64) =====
template <int EP>
__global__ void __launch_bounds__(256, 2)
mma_gemmA(const fp16* __restrict__ Ah, long long lda,
          const fp16* __restrict__ Bh, const fp16* __restrict__ Bl,
          long long ldb,
          const float* __restrict__ bias,
          float* __restrict__ Cf, long long ldc,
          int M, int Ntiles, int KC) {
    constexpr unsigned STAGE = 3 * PL64;
    extern __shared__ char smc[];
    unsigned smbase;
    asm("{ .reg .u64 t; cvta.to.shared.u64 t, %1; cvt.u32.u64 %0, t; }"
        : "=r"(smbase) : "l"(smc));

    const int tid = threadIdx.x, wid = tid >> 5, lane = tid & 31;
    const int g = lane >> 2, tg = lane & 3;
    const int wm = wid >> 2, wn = wid & 3;
    const int nt = blockIdx.x % Ntiles, mt = blockIdx.x / Ntiles;
    const int n0 = nt * 128, m0 = mt * 128;

    const int s4 = lane >> 3, lr = lane & 7;
    const int aRowL = lr + (s4 & 1) * 8, aColL = (s4 >> 1) * 8;
    const int bRowL = lr + (s4 >> 1) * 8, bColL = (s4 & 1) * 8;

    float acc[4][4][4];
#pragma unroll
    for (int i = 0; i < 4; i++)
#pragma unroll
        for (int j = 0; j < 4; j++)
#pragma unroll
            for (int r = 0; r < 4; r++) acc[i][j][r] = 0.f;

    auto issue = [&](int c) {
        const int k0 = c * 64;
        unsigned sb = smbase + (c & 1) * STAGE;
#pragma unroll
        for (int i = 0; i < 4; i++) {
            int item = tid + i * 256;
            int row = item >> 3, c8 = item & 7;
            int m = m0 + row;
            int sz = (m < M) ? 16 : 0;
            size_t go = (size_t)(m < M ? m : 0) * lda + k0 + c8 * 8;
            cpa16(sb + row * 144 + c8 * 16, Ah + go, sz);
        }
#pragma unroll
        for (int i = 0; i < 4; i++) {
            int item = tid + i * 256;
            int row = item >> 3, c8 = item & 7;
            size_t go = (size_t)(n0 + row) * ldb + k0 + c8 * 8;
            unsigned so = sb + PL64 + row * 144 + c8 * 16;
            cpa16(so, Bh + go, 16);
            cpa16(so + PL64, Bl + go, 16);
        }
    };

    issue(0);
    CPA_COMMIT();

    for (int c = 0; c < KC; ++c) {
        if (c + 1 < KC) { issue(c + 1); CPA_COMMIT(); CPA_WAIT(1); }
        else            { CPA_WAIT(0); }
        __syncthreads();

        unsigned sb = smbase + (c & 1) * STAGE;
        unsigned sbB = sb + PL64;
#pragma unroll
        for (int ks = 0; ks < 4; ks++) {
            const int kb = ks * 16;
            unsigned bh_[4][2], bl_[4][2];
#pragma unroll
            for (int p = 0; p < 2; p++) {
                int rn0 = wn * 32 + p * 16;
                unsigned ba = sbB + (unsigned)((rn0 + bRowL) * STR64 + kb + bColL) * 2;
                LDSM4(bh_[2 * p][0], bh_[2 * p][1], bh_[2 * p + 1][0], bh_[2 * p + 1][1], ba);
                LDSM4(bl_[2 * p][0], bl_[2 * p][1], bl_[2 * p + 1][0], bl_[2 * p + 1][1],
                      ba + PL64);
            }
#pragma unroll
            for (int mi = 0; mi < 4; mi++) {
                int rm0 = wm * 64 + mi * 16;
                unsigned aa = sb + (unsigned)((rm0 + aRowL) * STR64 + kb + aColL) * 2;
                unsigned ah_[4];
                LDSM4(ah_[0], ah_[1], ah_[2], ah_[3], aa);
#pragma unroll
                for (int ni = 0; ni < 4; ni++) {
                    mma16816(acc[mi][ni], ah_, bh_[ni]);
                    mma16816(acc[mi][ni], ah_, bl_[ni]);
                }
            }
        }
        __syncthreads();
    }

    float* sOut = (float*)smc;
#pragma unroll
    for (int mi = 0; mi < 4; mi++) {
        int lrow = wm * 64 + mi * 16 + g;
#pragma unroll
        for (int ni = 0; ni < 4; ni++) {
            int j = wn * 32 + ni * 8 + tg * 2;
            float b0 = 0.f, b1 = 0.f;
            if (EP == 2) { b0 = bias[n0 + j]; b1 = bias[n0 + j + 1]; }
#pragma unroll
            for (int hh = 0; hh < 2; hh++) {
                float v0 = acc[mi][ni][hh * 2 + 0] + b0;
                float v1 = acc[mi][ni][hh * 2 + 1] + b1;
                *(float2*)&sOut[(lrow + hh * 8) * 132 + j] = make_float2(v0, v1);
            }
        }
    }
    __syncthreads();
#pragma unroll
    for (int i = 0; i < 16; i++) {
        int item = tid + i * 256;
        int row = item >> 5;
        int c4 = (item & 31) * 4;
        int m = m0 + row;
        if (m >= M) continue;
        float4 v = *(float4*)&sOut[row * 132 + c4];
        float* p = Cf + (size_t)m * ldc + n0 + c4;
        if (EP == 2) {
            float4 old = *(float4*)p;
            v.x += old.x; v.y += old.y; v.z += old.z; v.w += old.w;
        }
        *(float4*)p = v;
    }
}

// ======================= NT1 MoE GEMM, 256x128 tile (K-chunk 64) ============
// EP: 3 = gelu(+bias) -> fp16 Ch; 4 = +bias -> fp16 Ch
#define APL256 (256 * 144)             // 36864
#define STAGE256 (APL256 + 128 * 144)  // 55296
#define SMEM_256 (2 * STAGE256)        // 110592

template <int EP>
__global__ void __launch_bounds__(256, 1)
mma_gemm256(const fp16* __restrict__ Ah, long long lda, long long aExp,
            const fp16* __restrict__ Bh, long long ldb, long long bExp,
            const float* __restrict__ bias, long long biasExp,
            fp16* __restrict__ Ch, long long ldc, long long cExp,
            int M, int Ntiles, int KC) {
    extern __shared__ char smc[];
    unsigned smbase;
    asm("{ .reg .u64 t; cvta.to.shared.u64 t, %1; cvt.u32.u64 %0, t; }"
        : "=r"(smbase) : "l"(smc));

    const int tid = threadIdx.x, wid = tid >> 5, lane = tid & 31;
    const int g = lane >> 2, tg = lane & 3;
    const int wm = wid >> 1, wn = wid & 1;       // 4x1 warps of 64M x 64N... (8 warps: 4 wm x 2 wn)
    const int e = blockIdx.y;
    const int nt = blockIdx.x % Ntiles, mt = blockIdx.x / Ntiles;
    const int n0 = nt * 128, m0 = mt * 256;

    const fp16* Abh = Ah + (size_t)e * aExp;
    const fp16* Bbh = Bh + (size_t)e * bExp;

    const int s4 = lane >> 3, lr = lane & 7;
    const int aRowL = lr + (s4 & 1) * 8, aColL = (s4 >> 1) * 8;
    const int bRowL = lr + (s4 >> 1) * 8, bColL = (s4 & 1) * 8;

    float acc[4][8][4];
#pragma unroll
    for (int i = 0; i < 4; i++)
#pragma unroll
        for (int j = 0; j < 8; j++)
#pragma unroll
            for (int r = 0; r < 4; r++) acc[i][j][r] = 0.f;

    auto issue = [&](int c) {
        const int k0 = c * 64;
        unsigned sb = smbase + (c & 1) * STAGE256;
        // A: 256 rows x 128B
#pragma unroll
        for (int i = 0; i < 8; i++) {
            int item = tid + i * 256;
            int row = item >> 3, c8 = item & 7;
            int m = m0 + row;
            int sz = (m < M) ? 16 : 0;
            size_t go = (size_t)(m < M ? m : 0) * lda + k0 + c8 * 8;
            cpa16(sb + row * 144 + c8 * 16, Abh + go, sz);
        }
        // B: 128 rows x 128B
#pragma unroll
        for (int i = 0; i < 4; i++) {
            int item = tid + i * 256;
            int row = item >> 3, c8 = item & 7;
            size_t go = (size_t)(n0 + row) * ldb + k0 + c8 * 8;
            cpa16(sb + APL256 + row * 144 + c8 * 16, Bbh + go, 16);
        }
    };

    issue(0);
    CPA_COMMIT();

    for (int c = 0; c < KC; ++c) {
        if (c + 1 < KC) { issue(c + 1); CPA_COMMIT(); CPA_WAIT(1); }
        else            { CPA_WAIT(0); }
        __syncthreads();

        unsigned sb = smbase + (c & 1) * STAGE256;
        unsigned sbB = sb + APL256;
#pragma unroll
        for (int ks = 0; ks < 4; ks++) {
            const int kb = ks * 16;
            unsigned bh_[8][2];
#pragma unroll
            for (int p = 0; p < 4; p++) {
                int rn0 = wn * 64 + p * 16;
                unsigned ba = sbB + (unsigned)((rn0 + bRowL) * STR64 + kb + bColL) * 2;
                LDSM4(bh_[2 * p][0], bh_[2 * p][1], bh_[2 * p + 1][0], bh_[2 * p + 1][1], ba);
            }
#pragma unroll
            for (int mi = 0; mi < 4; mi++) {
                int rm0 = wm * 64 + mi * 16;
                unsigned aa = sb + (unsigned)((rm0 + aRowL) * STR64 + kb + aColL) * 2;
                unsigned ah_[4];
                LDSM4(ah_[0], ah_[1], ah_[2], ah_[3], aa);
#pragma unroll
                for (int ni = 0; ni < 8; ni++)
                    mma16816(acc[mi][ni], ah_, bh_[ni]);
            }
        }
        __syncthreads();
    }

    // ---- epilogue: two 128-row passes through smem ----
    float* sOut = (float*)smc;
#pragma unroll
    for (int half = 0; half < 2; half++) {
        if ((wm >> 1) == half) {
#pragma unroll
            for (int mi = 0; mi < 4; mi++) {
                int lrow = (wm & 1) * 64 + mi * 16 + g;
#pragma unroll
                for (int ni = 0; ni < 8; ni++) {
                    int j = wn * 64 + ni * 8 + tg * 2;
                    float b0 = bias[(size_t)e * biasExp + n0 + j];
                    float b1 = bias[(size_t)e * biasExp + n0 + j + 1];
#pragma unroll
                    for (int hh = 0; hh < 2; hh++) {
                        float v0 = acc[mi][ni][hh * 2 + 0] + b0;
                        float v1 = acc[mi][ni][hh * 2 + 1] + b1;
                        if (EP == 3) { v0 = gelu_exact(v0); v1 = gelu_exact(v1); }
                        *(float2*)&sOut[(lrow + hh * 8) * 132 + j] = make_float2(v0, v1);
                    }
                }
            }
        }
        __syncthreads();
        int m0h = m0 + half * 128;
#pragma unroll
        for (int i = 0; i < 8; i++) {
            int item = tid + i * 256;
            int row = item >> 4;
            int c8 = (item & 15) * 8;
            int m = m0h + row;
            if (m < M) {
                float4 f0 = *(float4*)&sOut[row * 132 + c8];
                float4 f1 = *(float4*)&sOut[row * 132 + c8 + 4];
                __half2 h0 = __floats2half2_rn(f0.x, f0.y);
                __half2 h1 = __floats2half2_rn(f0.z, f0.w);
                __half2 h2 = __floats2half2_rn(f1.x, f1.y);
                __half2 h3 = __floats2half2_rn(f1.z, f1.w);
                uint4 u = make_uint4(*(unsigned*)&h0, *(unsigned*)&h1,
                                     *(unsigned*)&h2, *(unsigned*)&h3);
                *(uint4*)(Ch + (size_t)e * cExp + (size_t)m * ldc + n0 + c8) = u;
            }
        }
        __syncthreads();
    }
}

// ======================= transpose + split convert (64x64 tiles) ============
template <int LO>
__global__ void __launch_bounds__(256)
convT(const float* __restrict__ src, long long sExp, int K, int N,
      fp16* __restrict__ th, fp16* __restrict__ tl, long long tExp) {
    __shared__ float t[64][65];
    int e = blockIdx.z;
    int k0 = blockIdx.x * 64, nn0 = blockIdx.y * 64;
    const float* sp = src + (size_t)e * sExp;
    {
        int rrow = threadIdx.x >> 4;
        int c4 = (threadIdx.x & 15) * 4;
#pragma unroll
        for (int r = 0; r < 4; r++) {
            int k = rrow + r * 16;
            float4 v = *(const float4*)(sp + (size_t)(k0 + k) * N + nn0 + c4);
            t[k][c4 + 0] = v.x; t[k][c4 + 1] = v.y;
            t[k][c4 + 2] = v.z; t[k][c4 + 3] = v.w;
        }
    }
    __syncthreads();
    {
        int n = threadIdx.x >> 2;
        int kq = (threadIdx.x & 3) * 16;
        size_t o = (size_t)e * tExp + (size_t)(nn0 + n) * K + k0 + kq;
#pragma unroll
        for (int i = 0; i < 4; i++) {
            float v0 = t[kq + i * 4 + 0][n], v1 = t[kq + i * 4 + 1][n];
            float v2 = t[kq + i * 4 + 2][n], v3 = t[kq + i * 4 + 3][n];
            __half2 h0 = __floats2half2_rn(v0, v1);
            __half2 h1 = __floats2half2_rn(v2, v3);
            *(uint2*)(th + o + i * 4) = make_uint2(*(unsigned*)&h0, *(unsigned*)&h1);
            if (LO) {
                float2 r0 = __half22float2(h0), r1 = __half22float2(h1);
                __half2 l0 = __floats2half2_rn(v0 - r0.x, v1 - r0.y);
                __half2 l1 = __floats2half2_rn(v2 - r1.x, v3 - r1.y);
                *(uint2*)(tl + o + i * 4) = make_uint2(*(unsigned*)&l0, *(unsigned*)&l1);
            }
        }
    }
}

// ======================= gate_w transpose =======================
__global__ void gwT_kernel(const float* __restrict__ gw, float* __restrict__ gwT) {
    int i = blockIdx.x * blockDim.x + threadIdx.x;
    if (i >= NE * CDIM) return;
    int e = i / CDIM, c = i % CDIM;
    gwT[i] = gw[c * NE + e];
}

// ======================= pack Wq/Wk/Wv -> [3C][C] fp16 hi/lo =================
__global__ void pack_qkvT(const float* __restrict__ Wq,
                          const float* __restrict__ Wk,
                          const float* __restrict__ Wv,
                          fp16* __restrict__ th, fp16* __restrict__ tl) {
    int j = blockIdx.x;
    int which = j / CDIM, hs = j % CDIM;
    int h = hs / HSD, s = hs % HSD;
    const float* W = (which == 0) ? Wq : ((which == 1) ? Wk : Wv);
    for (int c = threadIdx.x; c < CDIM; c += 256) {
        float v = W[((size_t)h * CDIM + c) * HSD + s];
        fp16 hi = __float2half_rn(v);
        size_t o = (size_t)j * CDIM + c;
        th[o] = hi;
        tl[o] = __float2half_rn(v - __half2float(hi));
    }
}

// ======================= embedding =======================
__global__ void embed_kernel(const int* __restrict__ idx,
                             const float* __restrict__ tok,
                             const float* __restrict__ pos,
                             float* __restrict__ x) {
    int n = blockIdx.x;
    int t = n % TSEQ;
    int v = idx[n];
    for (int c = threadIdx.x; c < CDIM; c += blockDim.x)
        x[n * CDIM + c] = tok[v * CDIM + c] + pos[t * CDIM + c];
}

// ======================= layernorm =======================
__global__ void ln_kernel(const float* __restrict__ x,
                          const float* __restrict__ g,
                          const float* __restrict__ b,
                          float* __restrict__ out,
                          fp16* __restrict__ oh) {
    int n = blockIdx.x;
    int tid = threadIdx.x;
    __shared__ float s1[256], s2[256];
    const float* xr = x + (size_t)n * CDIM;
    float a = 0.f, q = 0.f;
    for (int c = tid; c < CDIM; c += 256) { float v = xr[c]; a += v; q += v * v; }
    s1[tid] = a; s2[tid] = q;
    __syncthreads();
    for (int s = 128; s > 0; s >>= 1) {
        if (tid < s) { s1[tid] += s1[tid + s]; s2[tid] += s2[tid + s]; }
        __syncthreads();
    }
    float mean = s1[0] * (1.f / CDIM);
    float var  = s2[0] * (1.f / CDIM) - mean * mean;
    float r = rsqrtf(var + 1e-5f);
    for (int c = tid; c < CDIM; c += 256) {
        float o = (xr[c] - mean) * r * g[c] + b[c];
        size_t p = (size_t)n * CDIM + c;
        out[p] = o;
        oh[p] = __float2half_rn(o);
    }
}

// ======================= attention v2 =======================
#define KV_STR 25
#define ATTN_SMEM ((TSEQ * KV_STR * 2 + 8 * 424 + 8 * 24) * 4)

__global__ void __launch_bounds__(256)
attn2_kernel(const float* __restrict__ qkv, fp16* __restrict__ atth) {
    int h = blockIdx.x, b = blockIdx.y;
    extern __shared__ float sm[];
    float* Ks = sm;
    float* Vs = Ks + TSEQ * KV_STR;
    float* sc = Vs + TSEQ * KV_STR;
    float* qb = sc + 8 * 424;

    int tid = threadIdx.x, wid = tid >> 5, lane = tid & 31;
    int n0 = b * TSEQ;

    for (int i = tid; i < TSEQ * HSD; i += 256) {
        int u = i / HSD, s = i - u * HSD;
        const float* base = qkv + (size_t)(n0 + u) * (3 * CDIM) + h * HSD + s;
        Ks[u * KV_STR + s] = base[CDIM];
        Vs[u * KV_STR + s] = base[2 * CDIM];
    }
    __syncthreads();

    const float scale = 0.20412414523193154f;
    float* scw = sc + wid * 424;
    float* qw  = qb + wid * 24;

    for (int t = wid; t < TSEQ; t += 8) {
        if (lane < HSD)
            qw[lane] = qkv[(size_t)(n0 + t) * (3 * CDIM) + h * HSD + lane];
        __syncwarp();

        float lmax = -1e30f;
        for (int u = lane; u <= t; u += 32) {
            const float* kr = Ks + u * KV_STR;
            float d = 0.f;
#pragma unroll
            for (int s = 0; s < HSD; s++) d += qw[s] * kr[s];
            d *= scale;
            scw[u] = d;
            lmax = fmaxf(lmax, d);
        }
        for (int o = 16; o > 0; o >>= 1)
            lmax = fmaxf(lmax, __shfl_xor_sync(0xFFFFFFFFu, lmax, o));

        float lsum = 0.f;
        for (int u = lane; u <= t; u += 32) {
            float ev = expf(scw[u] - lmax);
            scw[u] = ev;
            lsum += ev;
        }
        for (int o = 16; o > 0; o >>= 1)
            lsum += __shfl_xor_sync(0xFFFFFFFFu, lsum, o);
        float inv = 1.f / lsum;
        __syncwarp();

        if (lane < HSD) {
            float a = 0.f;
            for (int u = 0; u <= t; u++)
                a += scw[u] * Vs[u * KV_STR + lane];
            a *= inv;
            atth[(size_t)(n0 + t) * CDIM + h * HSD + lane] = __float2half_rn(a);
        }
        __syncwarp();
    }
}

// ======================= gate softmax v2 =======================
__global__ void __launch_bounds__(256)
gate2_kernel(const float* __restrict__ h2, const float* __restrict__ gwT,
             const float* __restrict__ gb, float* __restrict__ gates) {
    int n = blockIdx.x;
    int tid = threadIdx.x, wid = tid >> 5, lane = tid & 31;
    __shared__ float lg[NE];
    __shared__ float hsm[CDIM];
    for (int c = tid; c < CDIM; c += 256) hsm[c] = h2[(size_t)n * CDIM + c];
    __syncthreads();
    for (int e = wid; e < NE; e += 8) {
        const float* w = gwT + (size_t)e * CDIM;
        float a = 0.f;
        for (int c = lane; c < CDIM; c += 32) a += hsm[c] * w[c];
        for (int o = 16; o > 0; o >>= 1) a += __shfl_xor_sync(0xFFFFFFFFu, a, o);
        if (lane == 0) lg[e] = a + gb[e];
    }
    __syncthreads();
    if (tid < 32) {
        float v = lg[tid];
        float mx = v;
        for (int o = 16; o > 0; o >>= 1) mx = fmaxf(mx, __shfl_xor_sync(0xFFFFFFFFu, mx, o));
        float ex = expf(v - mx);
        float smv = ex;
        for (int o = 16; o > 0; o >>= 1) smv += __shfl_xor_sync(0xFFFFFFFFu, smv, o);
        gates[n * NE + tid] = ex / smv;
    }
}

// ======================= MoE combine (fp16 eo) =======================
__global__ void combine_kernel(const fp16* __restrict__ eo,
                               const float* __restrict__ gates,
                               float* __restrict__ x) {
    int n = blockIdx.x;
    __shared__ float gs[NE];
    if (threadIdx.x < NE) gs[threadIdx.x] = gates[n * NE + threadIdx.x];
    __syncthreads();
    for (int c = threadIdx.x; c < CDIM; c += blockDim.x) {
        float a = 0.f;
        const fp16* er = eo + (size_t)n * (NE * CDIM) + c;
#pragma unroll 8
        for (int e = 0; e < NE; e++) a += gs[e] * __half2float(er[e * CDIM]);
        x[(size_t)n * CDIM + c] += a;
    }
}

// ======================= scalar SGEMM (lm head only) =======================
__global__ void __launch_bounds__(256)
lm_head_kernel(const float* __restrict__ A, const float* __restrict__ B,
               const float* __restrict__ bias, float* __restrict__ C,
               int M, int N, int K) {
    __shared__ float As[64][17];
    __shared__ float Bs[16][64];
    int tid = threadIdx.x;
    int jTile = blockIdx.x * 64;
    int mTile = blockIdx.y * 64;
    int tx = tid & 15, ty = tid >> 4;

    float acc[4][4];
#pragma unroll
    for (int r = 0; r < 4; r++)
#pragma unroll
        for (int c = 0; c < 4; c++) acc[r][c] = 0.f;

    int aRow = tid >> 2, aK = (tid & 3) * 4;
    int bJ = tid & 63, bK0 = tid >> 6;

    for (int k0 = 0; k0 < K; k0 += 16) {
        int m = mTile + aRow;
        if (m < M) {
            float4 av = *(const float4*)(A + (size_t)m * K + k0 + aK);
            As[aRow][aK + 0] = av.x; As[aRow][aK + 1] = av.y;
            As[aRow][aK + 2] = av.z; As[aRow][aK + 3] = av.w;
        } else {
            As[aRow][aK + 0] = 0.f; As[aRow][aK + 1] = 0.f;
            As[aRow][aK + 2] = 0.f; As[aRow][aK + 3] = 0.f;
        }
#pragma unroll
        for (int i = 0; i < 4; i++) {
            int kk = bK0 + i * 4;
            Bs[kk][bJ] = (jTile + bJ < N)
                ? B[(size_t)(k0 + kk) * N + jTile + bJ] : 0.f;
        }
        __syncthreads();
#pragma unroll
        for (int k = 0; k < 16; k++) {
            float4 bv = *(const float4*)&Bs[k][tx * 4];
            float a0 = As[ty * 4 + 0][k], a1 = As[ty * 4 + 1][k];
            float a2 = As[ty * 4 + 2][k], a3 = As[ty * 4 + 3][k];
            acc[0][0] += a0 * bv.x; acc[0][1] += a0 * bv.y; acc[0][2] += a0 * bv.z; acc[0][3] += a0 * bv.w;
            acc[1][0] += a1 * bv.x; acc[1][1] += a1 * bv.y; acc[1][2] += a1 * bv.z; acc[1][3] += a1 * bv.w;
            acc[2][0] += a2 * bv.x; acc[2][1] += a2 * bv.y; acc[2][2] += a2 * bv.z; acc[2][3] += a2 * bv.w;
            acc[3][0] += a3 * bv.x; acc[3][1] += a3 * bv.y; acc[3][2] += a3 * bv.z; acc[3][3] += a3 * bv.w;
        }
        __syncthreads();
    }
#pragma unroll
    for (int r = 0; r < 4; r++) {
        int m = mTile + ty * 4 + r;
        if (m >= M) continue;
#pragma unroll
        for (int c = 0; c < 4; c++) {
            int j = jTile + tx * 4 + c;
            if (j >= N) continue;
            C[(size_t)m * N + j] = acc[r][c] + bias[j];
        }
    }
}

// ======================= launch =======================
extern "C" void kernel_launch(void* const* d_in, const int* in_sizes, int n_in,
                              void* d_out, int out_size) {
    const int*   idx    = (const int*)  d_in[0];
    const float* tok    = (const float*)d_in[1];
    const float* pos    = (const float*)d_in[2];
    const float* ln1_g  = (const float*)d_in[3];
    const float* ln1_b  = (const float*)d_in[4];
    const float* Wq     = (const float*)d_in[5];
    const float* Wk     = (const float*)d_in[6];
    const float* Wv     = (const float*)d_in[7];
    const float* Wo     = (const float*)d_in[8];
    const float* bo     = (const float*)d_in[9];
    const float* ln2_g  = (const float*)d_in[10];
    const float* ln2_b  = (const float*)d_in[11];
    const float* gate_w = (const float*)d_in[12];
    const float* gate_b = (const float*)d_in[13];
    const float* W1     = (const float*)d_in[14];
    const float* b1     = (const float*)d_in[15];
    const float* W2     = (const float*)d_in[16];
    const float* b2     = (const float*)d_in[17];
    const float* lnf_g  = (const float*)d_in[18];
    const float* lnf_b  = (const float*)d_in[19];
    const float* lm_w   = (const float*)d_in[20];
    const float* lm_b   = (const float*)d_in[21];
    float* out = (float*)d_out;

    float *x, *h, *qkv, *gates, *gwT;
    fp16 *eo, *hh, *atth, *wpth, *wptl, *woth, *wotl;
    fp16 *w1th, *w2th, *hidh;
    cudaGetSymbolAddress((void**)&x,     g_x);
    cudaGetSymbolAddress((void**)&h,     g_h);
    cudaGetSymbolAddress((void**)&qkv,   g_qkv);
    cudaGetSymbolAddress((void**)&gates, g_gates);
    cudaGetSymbolAddress((void**)&gwT,   g_gwT);
    cudaGetSymbolAddress((void**)&eo,    g_eo);
    cudaGetSymbolAddress((void**)&hh,    g_hh);
    cudaGetSymbolAddress((void**)&atth,  g_atth);
    cudaGetSymbolAddress((void**)&wpth,  g_wpth);
    cudaGetSymbolAddress((void**)&wptl,  g_wptl);
    cudaGetSymbolAddress((void**)&woth,  g_woth);
    cudaGetSymbolAddress((void**)&wotl,  g_wotl);
    cudaGetSymbolAddress((void**)&w1th,  g_w1th);
    cudaGetSymbolAddress((void**)&w2th,  g_w2th);
    cudaGetSymbolAddress((void**)&hidh,  g_hidh);

    cudaFuncSetAttribute(mma_gemmA<0>, cudaFuncAttributeMaxDynamicSharedMemorySize, SMEM_3PL);
    cudaFuncSetAttribute(mma_gemmA<2>, cudaFuncAttributeMaxDynamicSharedMemorySize, SMEM_3PL);
    cudaFuncSetAttribute(mma_gemm256<3>, cudaFuncAttributeMaxDynamicSharedMemorySize, SMEM_256);
    cudaFuncSetAttribute(mma_gemm256<4>, cudaFuncAttributeMaxDynamicSharedMemorySize, SMEM_256);
    cudaFuncSetAttribute(attn2_kernel, cudaFuncAttributeMaxDynamicSharedMemorySize, ATTN_SMEM);

    const int MT = (NTOK + 127) / 128;     // 7 (attn GEMMs)
    const int MT2 = (NTOK + 255) / 256;    // 4 (MoE GEMMs)

    // ---- pre-convert weights ----
    for (int l = 0; l < NL; l++) {
        convT<0><<<dim3(CDIM / 64, F4D / 64, NE), 256>>>(
            W1 + (size_t)l * NE * CDIM * F4D, (long long)CDIM * F4D, CDIM, F4D,
            w1th + (size_t)l * NE * F4D * CDIM, nullptr,
            (long long)F4D * CDIM);
        convT<0><<<dim3(F4D / 64, CDIM / 64, NE), 256>>>(
            W2 + (size_t)l * NE * F4D * CDIM, (long long)F4D * CDIM, F4D, CDIM,
            w2th + (size_t)l * NE * CDIM * F4D, nullptr,
            (long long)CDIM * F4D);
        convT<1><<<dim3(CDIM / 64, CDIM / 64, 1), 256>>>(
            Wo + (size_t)l * CDIM * CDIM, 0, CDIM, CDIM,
            woth + (size_t)l * CDIM * CDIM, wotl + (size_t)l * CDIM * CDIM, 0);
    }

    embed_kernel<<<NTOK, 256>>>(idx, tok, pos, x);

    for (int l = 0; l < NL; l++) {
        // --- attention ---
        ln_kernel<<<NTOK, 256>>>(x, ln1_g + l * CDIM, ln1_b + l * CDIM, h, hh);
        pack_qkvT<<<3 * CDIM, 256>>>(
            Wq + (size_t)l * NH * CDIM * HSD,
            Wk + (size_t)l * NH * CDIM * HSD,
            Wv + (size_t)l * NH * CDIM * HSD, wpth, wptl);
        mma_gemmA<0><<<dim3(MT * 18), 256, SMEM_3PL>>>(
            hh, CDIM, wpth, wptl, CDIM, nullptr,
            qkv, 3 * CDIM, NTOK, 18, CDIM / 64);
        attn2_kernel<<<dim3(NH, BSZ), 256, ATTN_SMEM>>>(qkv, atth);
        mma_gemmA<2><<<dim3(MT * 6), 256, SMEM_3PL>>>(
            atth, CDIM,
            woth + (size_t)l * CDIM * CDIM, wotl + (size_t)l * CDIM * CDIM, CDIM,
            bo + l * CDIM, x, CDIM, NTOK, 6, CDIM / 64);

        // --- MoE ---
        ln_kernel<<<NTOK, 256>>>(x, ln2_g + l * CDIM, ln2_b + l * CDIM, h, hh);
        gwT_kernel<<<(NE * CDIM + 255) / 256, 256>>>(
            gate_w + (size_t)l * CDIM * NE, gwT);
        gate2_kernel<<<NTOK, 256>>>(h, gwT, gate_b + l * NE, gates);
        mma_gemm256<3><<<dim3(MT2 * (F4D / 128), NE), 256, SMEM_256>>>(
            hh, CDIM, 0,
            w1th + (size_t)l * NE * F4D * CDIM, CDIM, (long long)F4D * CDIM,
            b1 + (size_t)l * NE * F4D, F4D,
            hidh, (long long)NE * F4D, F4D,
            NTOK, F4D / 128, CDIM / 64);
        mma_gemm256<4><<<dim3(MT2 * (CDIM / 128), NE), 256, SMEM_256>>>(
            hidh, (long long)NE * F4D, F4D,
            w2th + (size_t)l * NE * CDIM * F4D, F4D, (long long)CDIM * F4D,
            b2 + (size_t)l * NE * CDIM, CDIM,
            eo, (long long)NE * CDIM, CDIM,
            NTOK, CDIM / 128, F4D / 64);
        combine_kernel<<<NTOK, 256>>>(eo, gates, x);
    }

    // --- final LN + lm head ---
    ln_kernel<<<NTOK, 256>>>(x, lnf_g, lnf_b, h, hh);
    lm_head_kernel<<<dim3((NV + 63) / 64, (NTOK + 63) / 64), 256>>>(
        h, lm_w, lm_b, out, NTOK, NV, CDIM);
}

// round 15
// speedup vs baseline: 1.2519x; 1.2519x over previous
#include <cuda_runtime.h>
#include <cuda_fp16.h>
#include <math.h>
#include <stdint.h>

// ---- problem constants ----
#define NTOK 844      // B*T = 2*422
#define TSEQ 422
#define BSZ  2
#define CDIM 768
#define NH   32
#define HSD  24
#define NE   32
#define F4D  3072
#define NL   2
#define NV   100

typedef __half fp16;

// ---- device scratch ----
__device__ float g_x  [NTOK * CDIM];
__device__ float g_h  [NTOK * CDIM];
__device__ float g_qkv[NTOK * 3 * CDIM];
__device__ float g_gates[NTOK * NE];
__device__ float g_gwT[NE * CDIM];

__device__ fp16 g_eo [(size_t)NTOK * NE * CDIM];
__device__ fp16 g_hh [NTOK * CDIM];
__device__ fp16 g_atth[NTOK * CDIM];
__device__ fp16 g_wpth[3 * CDIM * CDIM], g_wptl[3 * CDIM * CDIM];
__device__ fp16 g_woth[NL * CDIM * CDIM], g_wotl[NL * CDIM * CDIM];
__device__ fp16 g_w1th[(size_t)NL * NE * F4D * CDIM];
__device__ fp16 g_w2th[(size_t)NL * NE * CDIM * F4D];
__device__ fp16 g_hidh[(size_t)NTOK * NE * F4D];

// ======================= helpers =======================
__device__ __forceinline__ float gelu_exact(float v) {
    return 0.5f * v * (1.f + erff(v * 0.70710678118654752f));
}

__device__ __forceinline__ void mma16816(float* d, const unsigned* a, const unsigned* b) {
    asm volatile(
        "mma.sync.aligned.m16n8k16.row.col.f32.f16.f16.f32 "
        "{%0,%1,%2,%3}, {%4,%5,%6,%7}, {%8,%9}, {%0,%1,%2,%3};"
        : "+f"(d[0]), "+f"(d[1]), "+f"(d[2]), "+f"(d[3])
        : "r"(a[0]), "r"(a[1]), "r"(a[2]), "r"(a[3]), "r"(b[0]), "r"(b[1]));
}

__device__ __forceinline__ void cpa16(unsigned s, const void* g, int sz) {
    asm volatile("cp.async.cg.shared.global [%0], [%1], 16, %2;"
                 :: "r"(s), "l"(g), "r"(sz));
}
#define CPA_COMMIT() asm volatile("cp.async.commit_group;" ::: "memory")
#define CPA_WAIT(n)  asm volatile("cp.async.wait_group %0;" :: "n"(n) : "memory")

#define LDSM4(r0, r1, r2, r3, addr)                                            \
    asm volatile("ldmatrix.sync.aligned.m8n8.x4.shared.b16 {%0,%1,%2,%3}, [%4];" \
        : "=r"(r0), "=r"(r1), "=r"(r2), "=r"(r3) : "r"(addr))

// ======================= shared GEMM geometry =======================
#define STR64 72
#define PL64 (128 * 144)
#define SMEM_3PL 110592            // attn NT2: 2 stages * 3 planes

// ======================= NT2 attention GEMM (A hi; B hi+lo; K-chunk 64) =====
template <int EP>
__global__ void __launch_bounds__(256, 2)
mma_gemmA(const fp16* __restrict__ Ah, long long lda,
          const fp16* __restrict__ Bh, const fp16* __restrict__ Bl,
          long long ldb,
          const float* __restrict__ bias,
          float* __restrict__ Cf, long long ldc,
          int M, int Ntiles, int KC) {
    constexpr unsigned STAGE = 3 * PL64;
    extern __shared__ char smc[];
    unsigned smbase;
    asm("{ .reg .u64 t; cvta.to.shared.u64 t, %1; cvt.u32.u64 %0, t; }"
        : "=r"(smbase) : "l"(smc));

    const int tid = threadIdx.x, wid = tid >> 5, lane = tid & 31;
    const int g = lane >> 2, tg = lane & 3;
    const int wm = wid >> 2, wn = wid & 3;
    const int nt = blockIdx.x % Ntiles, mt = blockIdx.x / Ntiles;
    const int n0 = nt * 128, m0 = mt * 128;

    const int s4 = lane >> 3, lr = lane & 7;
    const int aRowL = lr + (s4 & 1) * 8, aColL = (s4 >> 1) * 8;
    const int bRowL = lr + (s4 >> 1) * 8, bColL = (s4 & 1) * 8;

    float acc[4][4][4];
#pragma unroll
    for (int i = 0; i < 4; i++)
#pragma unroll
        for (int j = 0; j < 4; j++)
#pragma unroll
            for (int r = 0; r < 4; r++) acc[i][j][r] = 0.f;

    auto issue = [&](int c) {
        const int k0 = c * 64;
        unsigned sb = smbase + (c & 1) * STAGE;
#pragma unroll
        for (int i = 0; i < 4; i++) {
            int item = tid + i * 256;
            int row = item >> 3, c8 = item & 7;
            int m = m0 + row;
            int sz = (m < M) ? 16 : 0;
            size_t go = (size_t)(m < M ? m : 0) * lda + k0 + c8 * 8;
            cpa16(sb + row * 144 + c8 * 16, Ah + go, sz);
        }
#pragma unroll
        for (int i = 0; i < 4; i++) {
            int item = tid + i * 256;
            int row = item >> 3, c8 = item & 7;
            size_t go = (size_t)(n0 + row) * ldb + k0 + c8 * 8;
            unsigned so = sb + PL64 + row * 144 + c8 * 16;
            cpa16(so, Bh + go, 16);
            cpa16(so + PL64, Bl + go, 16);
        }
    };

    issue(0);
    CPA_COMMIT();

    for (int c = 0; c < KC; ++c) {
        if (c + 1 < KC) { issue(c + 1); CPA_COMMIT(); CPA_WAIT(1); }
        else            { CPA_WAIT(0); }
        __syncthreads();

        unsigned sb = smbase + (c & 1) * STAGE;
        unsigned sbB = sb + PL64;
#pragma unroll
        for (int ks = 0; ks < 4; ks++) {
            const int kb = ks * 16;
            unsigned bh_[4][2], bl_[4][2];
#pragma unroll
            for (int p = 0; p < 2; p++) {
                int rn0 = wn * 32 + p * 16;
                unsigned ba = sbB + (unsigned)((rn0 + bRowL) * STR64 + kb + bColL) * 2;
                LDSM4(bh_[2 * p][0], bh_[2 * p][1], bh_[2 * p + 1][0], bh_[2 * p + 1][1], ba);
                LDSM4(bl_[2 * p][0], bl_[2 * p][1], bl_[2 * p + 1][0], bl_[2 * p + 1][1],
                      ba + PL64);
            }
#pragma unroll
            for (int mi = 0; mi < 4; mi++) {
                int rm0 = wm * 64 + mi * 16;
                unsigned aa = sb + (unsigned)((rm0 + aRowL) * STR64 + kb + aColL) * 2;
                unsigned ah_[4];
                LDSM4(ah_[0], ah_[1], ah_[2], ah_[3], aa);
#pragma unroll
                for (int ni = 0; ni < 4; ni++) {
                    mma16816(acc[mi][ni], ah_, bh_[ni]);
                    mma16816(acc[mi][ni], ah_, bl_[ni]);
                }
            }
        }
        __syncthreads();
    }

    float* sOut = (float*)smc;
#pragma unroll
    for (int mi = 0; mi < 4; mi++) {
        int lrow = wm * 64 + mi * 16 + g;
#pragma unroll
        for (int ni = 0; ni < 4; ni++) {
            int j = wn * 32 + ni * 8 + tg * 2;
            float b0 = 0.f, b1 = 0.f;
            if (EP == 2) { b0 = bias[n0 + j]; b1 = bias[n0 + j + 1]; }
#pragma unroll
            for (int hh = 0; hh < 2; hh++) {
                float v0 = acc[mi][ni][hh * 2 + 0] + b0;
                float v1 = acc[mi][ni][hh * 2 + 1] + b1;
                *(float2*)&sOut[(lrow + hh * 8) * 132 + j] = make_float2(v0, v1);
            }
        }
    }
    __syncthreads();
#pragma unroll
    for (int i = 0; i < 16; i++) {
        int item = tid + i * 256;
        int row = item >> 5;
        int c4 = (item & 31) * 4;
        int m = m0 + row;
        if (m >= M) continue;
        float4 v = *(float4*)&sOut[row * 132 + c4];
        float* p = Cf + (size_t)m * ldc + n0 + c4;
        if (EP == 2) {
            float4 old = *(float4*)p;
            v.x += old.x; v.y += old.y; v.z += old.z; v.w += old.w;
        }
        *(float4*)p = v;
    }
}

// ======================= NT1 MoE GEMM (K-chunk 64, 3-stage pipeline) ========
// EP: 3 = gelu(+bias) -> fp16 Ch; 4 = +bias -> fp16 Ch
// 3 stages of (A plane + B plane) = 3 * 36864 = 110592 B; 2 CTAs/SM preserved.
#define ST64 (2 * PL64)            // 36864 per stage
#define SMEM_M3 (3 * ST64)         // 110592

template <int EP>
__global__ void __launch_bounds__(256, 2)
mma_gemm64(const fp16* __restrict__ Ah, long long lda, long long aExp,
           const fp16* __restrict__ Bh, long long ldb, long long bExp,
           const float* __restrict__ bias, long long biasExp,
           fp16* __restrict__ Ch, long long ldc, long long cExp,
           int M, int Ntiles, int KC) {
    extern __shared__ char smc[];
    unsigned smbase;
    asm("{ .reg .u64 t; cvta.to.shared.u64 t, %1; cvt.u32.u64 %0, t; }"
        : "=r"(smbase) : "l"(smc));

    const int tid = threadIdx.x, wid = tid >> 5, lane = tid & 31;
    const int g = lane >> 2, tg = lane & 3;
    const int wm = wid >> 2, wn = wid & 3;
    const int e = blockIdx.y;
    const int nt = blockIdx.x % Ntiles, mt = blockIdx.x / Ntiles;
    const int n0 = nt * 128, m0 = mt * 128;

    const fp16* Abh = Ah + (size_t)e * aExp;
    const fp16* Bbh = Bh + (size_t)e * bExp;

    const int s4 = lane >> 3, lr = lane & 7;
    const int aRowL = lr + (s4 & 1) * 8, aColL = (s4 >> 1) * 8;
    const int bRowL = lr + (s4 >> 1) * 8, bColL = (s4 & 1) * 8;

    float acc[4][4][4];
#pragma unroll
    for (int i = 0; i < 4; i++)
#pragma unroll
        for (int j = 0; j < 4; j++)
#pragma unroll
            for (int r = 0; r < 4; r++) acc[i][j][r] = 0.f;

    auto issue = [&](int c) {
        const int k0 = c * 64;
        unsigned sb = smbase + (unsigned)(c % 3) * ST64;
#pragma unroll
        for (int i = 0; i < 4; i++) {
            int item = tid + i * 256;
            int row = item >> 3, c8 = item & 7;
            int m = m0 + row;
            int sz = (m < M) ? 16 : 0;
            size_t go = (size_t)(m < M ? m : 0) * lda + k0 + c8 * 8;
            cpa16(sb + row * 144 + c8 * 16, Abh + go, sz);
        }
#pragma unroll
        for (int i = 0; i < 4; i++) {
            int item = tid + i * 256;
            int row = item >> 3, c8 = item & 7;
            size_t go = (size_t)(n0 + row) * ldb + k0 + c8 * 8;
            cpa16(sb + PL64 + row * 144 + c8 * 16, Bbh + go, 16);
        }
    };

    // prologue: 2 stages in flight
    issue(0); CPA_COMMIT();
    if (KC > 1) { issue(1); CPA_COMMIT(); }

    for (int c = 0; c < KC; ++c) {
        // outstanding groups: 2 while c < KC-1, 1 on the final chunk
        if (c + 1 < KC) { CPA_WAIT(1); }
        else            { CPA_WAIT(0); }
        __syncthreads();           // protects slot (c+2)%3 == (c-1)%3 reads
        if (c + 2 < KC) { issue(c + 2); CPA_COMMIT(); }

        unsigned sb = smbase + (unsigned)(c % 3) * ST64;
        unsigned sbB = sb + PL64;
#pragma unroll
        for (int ks = 0; ks < 4; ks++) {
            const int kb = ks * 16;
            unsigned bh_[4][2];
#pragma unroll
            for (int p = 0; p < 2; p++) {
                int rn0 = wn * 32 + p * 16;
                unsigned ba = sbB + (unsigned)((rn0 + bRowL) * STR64 + kb + bColL) * 2;
                LDSM4(bh_[2 * p][0], bh_[2 * p][1], bh_[2 * p + 1][0], bh_[2 * p + 1][1], ba);
            }
#pragma unroll
            for (int mi = 0; mi < 4; mi++) {
                int rm0 = wm * 64 + mi * 16;
                unsigned aa = sb + (unsigned)((rm0 + aRowL) * STR64 + kb + aColL) * 2;
                unsigned ah_[4];
                LDSM4(ah_[0], ah_[1], ah_[2], ah_[3], aa);
#pragma unroll
                for (int ni = 0; ni < 4; ni++)
                    mma16816(acc[mi][ni], ah_, bh_[ni]);
            }
        }
    }
    __syncthreads();               // all reads done before smem reuse

    float* sOut = (float*)smc;
#pragma unroll
    for (int mi = 0; mi < 4; mi++) {
        int lrow = wm * 64 + mi * 16 + g;
#pragma unroll
        for (int ni = 0; ni < 4; ni++) {
            int j = wn * 32 + ni * 8 + tg * 2;
            float b0 = bias[(size_t)e * biasExp + n0 + j];
            float b1 = bias[(size_t)e * biasExp + n0 + j + 1];
#pragma unroll
            for (int hh = 0; hh < 2; hh++) {
                float v0 = acc[mi][ni][hh * 2 + 0] + b0;
                float v1 = acc[mi][ni][hh * 2 + 1] + b1;
                if (EP == 3) { v0 = gelu_exact(v0); v1 = gelu_exact(v1); }
                *(float2*)&sOut[(lrow + hh * 8) * 132 + j] = make_float2(v0, v1);
            }
        }
    }
    __syncthreads();
#pragma unroll
    for (int i = 0; i < 8; i++) {
        int item = tid + i * 256;
        int row = item >> 4;
        int c8 = (item & 15) * 8;
        int m = m0 + row;
        if (m >= M) continue;
        float4 f0 = *(float4*)&sOut[row * 132 + c8];
        float4 f1 = *(float4*)&sOut[row * 132 + c8 + 4];
        __half2 h0 = __floats2half2_rn(f0.x, f0.y);
        __half2 h1 = __floats2half2_rn(f0.z, f0.w);
        __half2 h2 = __floats2half2_rn(f1.x, f1.y);
        __half2 h3 = __floats2half2_rn(f1.z, f1.w);
        uint4 u = make_uint4(*(unsigned*)&h0, *(unsigned*)&h1,
                             *(unsigned*)&h2, *(unsigned*)&h3);
        *(uint4*)(Ch + (size_t)e * cExp + (size_t)m * ldc + n0 + c8) = u;
    }
}

// ======================= transpose + split convert (64x64 tiles) ============
template <int LO>
__global__ void __launch_bounds__(256)
convT(const float* __restrict__ src, long long sExp, int K, int N,
      fp16* __restrict__ th, fp16* __restrict__ tl, long long tExp) {
    __shared__ float t[64][65];
    int e = blockIdx.z;
    int k0 = blockIdx.x * 64, nn0 = blockIdx.y * 64;
    const float* sp = src + (size_t)e * sExp;
    {
        int rrow = threadIdx.x >> 4;
        int c4 = (threadIdx.x & 15) * 4;
#pragma unroll
        for (int r = 0; r < 4; r++) {
            int k = rrow + r * 16;
            float4 v = *(const float4*)(sp + (size_t)(k0 + k) * N + nn0 + c4);
            t[k][c4 + 0] = v.x; t[k][c4 + 1] = v.y;
            t[k][c4 + 2] = v.z; t[k][c4 + 3] = v.w;
        }
    }
    __syncthreads();
    {
        int n = threadIdx.x >> 2;
        int kq = (threadIdx.x & 3) * 16;
        size_t o = (size_t)e * tExp + (size_t)(nn0 + n) * K + k0 + kq;
#pragma unroll
        for (int i = 0; i < 4; i++) {
            float v0 = t[kq + i * 4 + 0][n], v1 = t[kq + i * 4 + 1][n];
            float v2 = t[kq + i * 4 + 2][n], v3 = t[kq + i * 4 + 3][n];
            __half2 h0 = __floats2half2_rn(v0, v1);
            __half2 h1 = __floats2half2_rn(v2, v3);
            *(uint2*)(th + o + i * 4) = make_uint2(*(unsigned*)&h0, *(unsigned*)&h1);
            if (LO) {
                float2 r0 = __half22float2(h0), r1 = __half22float2(h1);
                __half2 l0 = __floats2half2_rn(v0 - r0.x, v1 - r0.y);
                __half2 l1 = __floats2half2_rn(v2 - r1.x, v3 - r1.y);
                *(uint2*)(tl + o + i * 4) = make_uint2(*(unsigned*)&l0, *(unsigned*)&l1);
            }
        }
    }
}

// ======================= gate_w transpose =======================
__global__ void gwT_kernel(const float* __restrict__ gw, float* __restrict__ gwT) {
    int i = blockIdx.x * blockDim.x + threadIdx.x;
    if (i >= NE * CDIM) return;
    int e = i / CDIM, c = i % CDIM;
    gwT[i] = gw[c * NE + e];
}

// ======================= pack Wq/Wk/Wv -> [3C][C] fp16 hi/lo =================
__global__ void pack_qkvT(const float* __restrict__ Wq,
                          const float* __restrict__ Wk,
                          const float* __restrict__ Wv,
                          fp16* __restrict__ th, fp16* __restrict__ tl) {
    int j = blockIdx.x;
    int which = j / CDIM, hs = j % CDIM;
    int h = hs / HSD, s = hs % HSD;
    const float* W = (which == 0) ? Wq : ((which == 1) ? Wk : Wv);
    for (int c = threadIdx.x; c < CDIM; c += 256) {
        float v = W[((size_t)h * CDIM + c) * HSD + s];
        fp16 hi = __float2half_rn(v);
        size_t o = (size_t)j * CDIM + c;
        th[o] = hi;
        tl[o] = __float2half_rn(v - __half2float(hi));
    }
}

// ======================= embedding =======================
__global__ void embed_kernel(const int* __restrict__ idx,
                             const float* __restrict__ tok,
                             const float* __restrict__ pos,
                             float* __restrict__ x) {
    int n = blockIdx.x;
    int t = n % TSEQ;
    int v = idx[n];
    for (int c = threadIdx.x; c < CDIM; c += blockDim.x)
        x[n * CDIM + c] = tok[v * CDIM + c] + pos[t * CDIM + c];
}

// ======================= layernorm =======================
__global__ void ln_kernel(const float* __restrict__ x,
                          const float* __restrict__ g,
                          const float* __restrict__ b,
                          float* __restrict__ out,
                          fp16* __restrict__ oh) {
    int n = blockIdx.x;
    int tid = threadIdx.x;
    __shared__ float s1[256], s2[256];
    const float* xr = x + (size_t)n * CDIM;
    float a = 0.f, q = 0.f;
    for (int c = tid; c < CDIM; c += 256) { float v = xr[c]; a += v; q += v * v; }
    s1[tid] = a; s2[tid] = q;
    __syncthreads();
    for (int s = 128; s > 0; s >>= 1) {
        if (tid < s) { s1[tid] += s1[tid + s]; s2[tid] += s2[tid + s]; }
        __syncthreads();
    }
    float mean = s1[0] * (1.f / CDIM);
    float var  = s2[0] * (1.f / CDIM) - mean * mean;
    float r = rsqrtf(var + 1e-5f);
    for (int c = tid; c < CDIM; c += 256) {
        float o = (xr[c] - mean) * r * g[c] + b[c];
        size_t p = (size_t)n * CDIM + c;
        out[p] = o;
        oh[p] = __float2half_rn(o);
    }
}

// ======================= attention v2 =======================
#define KV_STR 25
#define ATTN_SMEM ((TSEQ * KV_STR * 2 + 8 * 424 + 8 * 24) * 4)

__global__ void __launch_bounds__(256)
attn2_kernel(const float* __restrict__ qkv, fp16* __restrict__ atth) {
    int h = blockIdx.x, b = blockIdx.y;
    extern __shared__ float sm[];
    float* Ks = sm;
    float* Vs = Ks + TSEQ * KV_STR;
    float* sc = Vs + TSEQ * KV_STR;
    float* qb = sc + 8 * 424;

    int tid = threadIdx.x, wid = tid >> 5, lane = tid & 31;
    int n0 = b * TSEQ;

    for (int i = tid; i < TSEQ * HSD; i += 256) {
        int u = i / HSD, s = i - u * HSD;
        const float* base = qkv + (size_t)(n0 + u) * (3 * CDIM) + h * HSD + s;
        Ks[u * KV_STR + s] = base[CDIM];
        Vs[u * KV_STR + s] = base[2 * CDIM];
    }
    __syncthreads();

    const float scale = 0.20412414523193154f;
    float* scw = sc + wid * 424;
    float* qw  = qb + wid * 24;

    for (int t = wid; t < TSEQ; t += 8) {
        if (lane < HSD)
            qw[lane] = qkv[(size_t)(n0 + t) * (3 * CDIM) + h * HSD + lane];
        __syncwarp();

        float lmax = -1e30f;
        for (int u = lane; u <= t; u += 32) {
            const float* kr = Ks + u * KV_STR;
            float d = 0.f;
#pragma unroll
            for (int s = 0; s < HSD; s++) d += qw[s] * kr[s];
            d *= scale;
            scw[u] = d;
            lmax = fmaxf(lmax, d);
        }
        for (int o = 16; o > 0; o >>= 1)
            lmax = fmaxf(lmax, __shfl_xor_sync(0xFFFFFFFFu, lmax, o));

        float lsum = 0.f;
        for (int u = lane; u <= t; u += 32) {
            float ev = expf(scw[u] - lmax);
            scw[u] = ev;
            lsum += ev;
        }
        for (int o = 16; o > 0; o >>= 1)
            lsum += __shfl_xor_sync(0xFFFFFFFFu, lsum, o);
        float inv = 1.f / lsum;
        __syncwarp();

        if (lane < HSD) {
            float a = 0.f;
            for (int u = 0; u <= t; u++)
                a += scw[u] * Vs[u * KV_STR + lane];
            a *= inv;
            atth[(size_t)(n0 + t) * CDIM + h * HSD + lane] = __float2half_rn(a);
        }
        __syncwarp();
    }
}

// ======================= gate softmax v2 =======================
__global__ void __launch_bounds__(256)
gate2_kernel(const float* __restrict__ h2, const float* __restrict__ gwT,
             const float* __restrict__ gb, float* __restrict__ gates) {
    int n = blockIdx.x;
    int tid = threadIdx.x, wid = tid >> 5, lane = tid & 31;
    __shared__ float lg[NE];
    __shared__ float hsm[CDIM];
    for (int c = tid; c < CDIM; c += 256) hsm[c] = h2[(size_t)n * CDIM + c];
    __syncthreads();
    for (int e = wid; e < NE; e += 8) {
        const float* w = gwT + (size_t)e * CDIM;
        float a = 0.f;
        for (int c = lane; c < CDIM; c += 32) a += hsm[c] * w[c];
        for (int o = 16; o > 0; o >>= 1) a += __shfl_xor_sync(0xFFFFFFFFu, a, o);
        if (lane == 0) lg[e] = a + gb[e];
    }
    __syncthreads();
    if (tid < 32) {
        float v = lg[tid];
        float mx = v;
        for (int o = 16; o > 0; o >>= 1) mx = fmaxf(mx, __shfl_xor_sync(0xFFFFFFFFu, mx, o));
        float ex = expf(v - mx);
        float smv = ex;
        for (int o = 16; o > 0; o >>= 1) smv += __shfl_xor_sync(0xFFFFFFFFu, smv, o);
        gates[n * NE + tid] = ex / smv;
    }
}

// ======================= MoE combine (fp16 eo) =======================
__global__ void combine_kernel(const fp16* __restrict__ eo,
                               const float* __restrict__ gates,
                               float* __restrict__ x) {
    int n = blockIdx.x;
    __shared__ float gs[NE];
    if (threadIdx.x < NE) gs[threadIdx.x] = gates[n * NE + threadIdx.x];
    __syncthreads();
    for (int c = threadIdx.x; c < CDIM; c += blockDim.x) {
        float a = 0.f;
        const fp16* er = eo + (size_t)n * (NE * CDIM) + c;
#pragma unroll 8
        for (int e = 0; e < NE; e++) a += gs[e] * __half2float(er[e * CDIM]);
        x[(size_t)n * CDIM + c] += a;
    }
}

// ======================= scalar SGEMM (lm head only) =======================
__global__ void __launch_bounds__(256)
lm_head_kernel(const float* __restrict__ A, const float* __restrict__ B,
               const float* __restrict__ bias, float* __restrict__ C,
               int M, int N, int K) {
    __shared__ float As[64][17];
    __shared__ float Bs[16][64];
    int tid = threadIdx.x;
    int jTile = blockIdx.x * 64;
    int mTile = blockIdx.y * 64;
    int tx = tid & 15, ty = tid >> 4;

    float acc[4][4];
#pragma unroll
    for (int r = 0; r < 4; r++)
#pragma unroll
        for (int c = 0; c < 4; c++) acc[r][c] = 0.f;

    int aRow = tid >> 2, aK = (tid & 3) * 4;
    int bJ = tid & 63, bK0 = tid >> 6;

    for (int k0 = 0; k0 < K; k0 += 16) {
        int m = mTile + aRow;
        if (m < M) {
            float4 av = *(const float4*)(A + (size_t)m * K + k0 + aK);
            As[aRow][aK + 0] = av.x; As[aRow][aK + 1] = av.y;
            As[aRow][aK + 2] = av.z; As[aRow][aK + 3] = av.w;
        } else {
            As[aRow][aK + 0] = 0.f; As[aRow][aK + 1] = 0.f;
            As[aRow][aK + 2] = 0.f; As[aRow][aK + 3] = 0.f;
        }
#pragma unroll
        for (int i = 0; i < 4; i++) {
            int kk = bK0 + i * 4;
            Bs[kk][bJ] = (jTile + bJ < N)
                ? B[(size_t)(k0 + kk) * N + jTile + bJ] : 0.f;
        }
        __syncthreads();
#pragma unroll
        for (int k = 0; k < 16; k++) {
            float4 bv = *(const float4*)&Bs[k][tx * 4];
            float a0 = As[ty * 4 + 0][k], a1 = As[ty * 4 + 1][k];
            float a2 = As[ty * 4 + 2][k], a3 = As[ty * 4 + 3][k];
            acc[0][0] += a0 * bv.x; acc[0][1] += a0 * bv.y; acc[0][2] += a0 * bv.z; acc[0][3] += a0 * bv.w;
            acc[1][0] += a1 * bv.x; acc[1][1] += a1 * bv.y; acc[1][2] += a1 * bv.z; acc[1][3] += a1 * bv.w;
            acc[2][0] += a2 * bv.x; acc[2][1] += a2 * bv.y; acc[2][2] += a2 * bv.z; acc[2][3] += a2 * bv.w;
            acc[3][0] += a3 * bv.x; acc[3][1] += a3 * bv.y; acc[3][2] += a3 * bv.z; acc[3][3] += a3 * bv.w;
        }
        __syncthreads();
    }
#pragma unroll
    for (int r = 0; r < 4; r++) {
        int m = mTile + ty * 4 + r;
        if (m >= M) continue;
#pragma unroll
        for (int c = 0; c < 4; c++) {
            int j = jTile + tx * 4 + c;
            if (j >= N) continue;
            C[(size_t)m * N + j] = acc[r][c] + bias[j];
        }
    }
}

// ======================= launch =======================
extern "C" void kernel_launch(void* const* d_in, const int* in_sizes, int n_in,
                              void* d_out, int out_size) {
    const int*   idx    = (const int*)  d_in[0];
    const float* tok    = (const float*)d_in[1];
    const float* pos    = (const float*)d_in[2];
    const float* ln1_g  = (const float*)d_in[3];
    const float* ln1_b  = (const float*)d_in[4];
    const float* Wq     = (const float*)d_in[5];
    const float* Wk     = (const float*)d_in[6];
    const float* Wv     = (const float*)d_in[7];
    const float* Wo     = (const float*)d_in[8];
    const float* bo     = (const float*)d_in[9];
    const float* ln2_g  = (const float*)d_in[10];
    const float* ln2_b  = (const float*)d_in[11];
    const float* gate_w = (const float*)d_in[12];
    const float* gate_b = (const float*)d_in[13];
    const float* W1     = (const float*)d_in[14];
    const float* b1     = (const float*)d_in[15];
    const float* W2     = (const float*)d_in[16];
    const float* b2     = (const float*)d_in[17];
    const float* lnf_g  = (const float*)d_in[18];
    const float* lnf_b  = (const float*)d_in[19];
    const float* lm_w   = (const float*)d_in[20];
    const float* lm_b   = (const float*)d_in[21];
    float* out = (float*)d_out;

    float *x, *h, *qkv, *gates, *gwT;
    fp16 *eo, *hh, *atth, *wpth, *wptl, *woth, *wotl;
    fp16 *w1th, *w2th, *hidh;
    cudaGetSymbolAddress((void**)&x,     g_x);
    cudaGetSymbolAddress((void**)&h,     g_h);
    cudaGetSymbolAddress((void**)&qkv,   g_qkv);
    cudaGetSymbolAddress((void**)&gates, g_gates);
    cudaGetSymbolAddress((void**)&gwT,   g_gwT);
    cudaGetSymbolAddress((void**)&eo,    g_eo);
    cudaGetSymbolAddress((void**)&hh,    g_hh);
    cudaGetSymbolAddress((void**)&atth,  g_atth);
    cudaGetSymbolAddress((void**)&wpth,  g_wpth);
    cudaGetSymbolAddress((void**)&wptl,  g_wptl);
    cudaGetSymbolAddress((void**)&woth,  g_woth);
    cudaGetSymbolAddress((void**)&wotl,  g_wotl);
    cudaGetSymbolAddress((void**)&w1th,  g_w1th);
    cudaGetSymbolAddress((void**)&w2th,  g_w2th);
    cudaGetSymbolAddress((void**)&hidh,  g_hidh);

    cudaFuncSetAttribute(mma_gemmA<0>, cudaFuncAttributeMaxDynamicSharedMemorySize, SMEM_3PL);
    cudaFuncSetAttribute(mma_gemmA<2>, cudaFuncAttributeMaxDynamicSharedMemorySize, SMEM_3PL);
    cudaFuncSetAttribute(mma_gemm64<3>, cudaFuncAttributeMaxDynamicSharedMemorySize, SMEM_M3);
    cudaFuncSetAttribute(mma_gemm64<4>, cudaFuncAttributeMaxDynamicSharedMemorySize, SMEM_M3);
    cudaFuncSetAttribute(attn2_kernel, cudaFuncAttributeMaxDynamicSharedMemorySize, ATTN_SMEM);

    const int MT = (NTOK + 127) / 128;   // 7

    // ---- pre-convert weights ----
    for (int l = 0; l < NL; l++) {
        convT<0><<<dim3(CDIM / 64, F4D / 64, NE), 256>>>(
            W1 + (size_t)l * NE * CDIM * F4D, (long long)CDIM * F4D, CDIM, F4D,
            w1th + (size_t)l * NE * F4D * CDIM, nullptr,
            (long long)F4D * CDIM);
        convT<0><<<dim3(F4D / 64, CDIM / 64, NE), 256>>>(
            W2 + (size_t)l * NE * F4D * CDIM, (long long)F4D * CDIM, F4D, CDIM,
            w2th + (size_t)l * NE * CDIM * F4D, nullptr,
            (long long)CDIM * F4D);
        convT<1><<<dim3(CDIM / 64, CDIM / 64, 1), 256>>>(
            Wo + (size_t)l * CDIM * CDIM, 0, CDIM, CDIM,
            woth + (size_t)l * CDIM * CDIM, wotl + (size_t)l * CDIM * CDIM, 0);
    }

    embed_kernel<<<NTOK, 256>>>(idx, tok, pos, x);

    for (int l = 0; l < NL; l++) {
        // --- attention ---
        ln_kernel<<<NTOK, 256>>>(x, ln1_g + l * CDIM, ln1_b + l * CDIM, h, hh);
        pack_qkvT<<<3 * CDIM, 256>>>(
            Wq + (size_t)l * NH * CDIM * HSD,
            Wk + (size_t)l * NH * CDIM * HSD,
            Wv + (size_t)l * NH * CDIM * HSD, wpth, wptl);
        mma_gemmA<0><<<dim3(MT * 18), 256, SMEM_3PL>>>(
            hh, CDIM, wpth, wptl, CDIM, nullptr,
            qkv, 3 * CDIM, NTOK, 18, CDIM / 64);
        attn2_kernel<<<dim3(NH, BSZ), 256, ATTN_SMEM>>>(qkv, atth);
        mma_gemmA<2><<<dim3(MT * 6), 256, SMEM_3PL>>>(
            atth, CDIM,
            woth + (size_t)l * CDIM * CDIM, wotl + (size_t)l * CDIM * CDIM, CDIM,
            bo + l * CDIM, x, CDIM, NTOK, 6, CDIM / 64);

        // --- MoE ---
        ln_kernel<<<NTOK, 256>>>(x, ln2_g + l * CDIM, ln2_b + l * CDIM, h, hh);
        gwT_kernel<<<(NE * CDIM + 255) / 256, 256>>>(
            gate_w + (size_t)l * CDIM * NE, gwT);
        gate2_kernel<<<NTOK, 256>>>(h, gwT, gate_b + l * NE, gates);
        mma_gemm64<3><<<dim3(MT * (F4D / 128), NE), 256, SMEM_M3>>>(
            hh, CDIM, 0,
            w1th + (size_t)l * NE * F4D * CDIM, CDIM, (long long)F4D * CDIM,
            b1 + (size_t)l * NE * F4D, F4D,
            hidh, (long long)NE * F4D, F4D,
            NTOK, F4D / 128, CDIM / 64);
        mma_gemm64<4><<<dim3(MT * (CDIM / 128), NE), 256, SMEM_M3>>>(
            hidh, (long long)NE * F4D, F4D,
            w2th + (size_t)l * NE * CDIM * F4D, F4D, (long long)CDIM * F4D,
            b2 + (size_t)l * NE * CDIM, CDIM,
            eo, (long long)NE * CDIM, CDIM,
            NTOK, CDIM / 128, F4D / 64);
        combine_kernel<<<NTOK, 256>>>(eo, gates, x);
    }

    // --- final LN + lm head ---
    ln_kernel<<<NTOK, 256>>>(x, lnf_g, lnf_b, h, hh);
    lm_head_kernel<<<dim3((NV + 63) / 64, (NTOK + 63) / 64), 256>>>(
        h, lm_w, lm_b, out, NTOK, NV, CDIM);
}

// round 16
// speedup vs baseline: 1.3163x; 1.0515x over previous
#include <cuda_runtime.h>
#include <cuda_fp16.h>
#include <math.h>
#include <stdint.h>

// ---- problem constants ----
#define NTOK 844      // B*T = 2*422
#define TSEQ 422
#define BSZ  2
#define CDIM 768
#define NH   32
#define HSD  24
#define NE   32
#define F4D  3072
#define NL   2
#define NV   100

typedef __half fp16;

// ---- device scratch ----
__device__ float g_x  [NTOK * CDIM];
__device__ float g_h  [NTOK * CDIM];
__device__ float g_qkv[NTOK * 3 * CDIM];
__device__ float g_gates[NTOK * NE];
__device__ float g_gwT[NE * CDIM];

__device__ fp16 g_eo [(size_t)NTOK * NE * CDIM];
__device__ fp16 g_hh [NTOK * CDIM];
__device__ fp16 g_atth[NTOK * CDIM];
__device__ fp16 g_wpth[3 * CDIM * CDIM], g_wptl[3 * CDIM * CDIM];
__device__ fp16 g_woth[NL * CDIM * CDIM], g_wotl[NL * CDIM * CDIM];
__device__ fp16 g_w1th[(size_t)NL * NE * F4D * CDIM];
__device__ fp16 g_w2th[(size_t)NL * NE * CDIM * F4D];
__device__ fp16 g_hidh[(size_t)NTOK * NE * F4D];

// ======================= helpers =======================
__device__ __forceinline__ float gelu_exact(float v) {
    return 0.5f * v * (1.f + erff(v * 0.70710678118654752f));
}

__device__ __forceinline__ void mma16816(float* d, const unsigned* a, const unsigned* b) {
    asm volatile(
        "mma.sync.aligned.m16n8k16.row.col.f32.f16.f16.f32 "
        "{%0,%1,%2,%3}, {%4,%5,%6,%7}, {%8,%9}, {%0,%1,%2,%3};"
        : "+f"(d[0]), "+f"(d[1]), "+f"(d[2]), "+f"(d[3])
        : "r"(a[0]), "r"(a[1]), "r"(a[2]), "r"(a[3]), "r"(b[0]), "r"(b[1]));
}

__device__ __forceinline__ void cpa16(unsigned s, const void* g, int sz) {
    asm volatile("cp.async.cg.shared.global [%0], [%1], 16, %2;"
                 :: "r"(s), "l"(g), "r"(sz));
}
#define CPA_COMMIT() asm volatile("cp.async.commit_group;" ::: "memory")
#define CPA_WAIT(n)  asm volatile("cp.async.wait_group %0;" :: "n"(n) : "memory")

#define LDSM4(r0, r1, r2, r3, addr)                                            \
    asm volatile("ldmatrix.sync.aligned.m8n8.x4.shared.b16 {%0,%1,%2,%3}, [%4];" \
        : "=r"(r0), "=r"(r1), "=r"(r2), "=r"(r3) : "r"(addr))

// ======================= shared GEMM geometry =======================
#define STR64 72
#define PL64 (128 * 144)
#define SMEM_3PL 110592            // attn NT2: 2 stages * 3 planes
#define SMEM_2PL  73728            // MoE NT1: 2 stages * 2 planes

// ======================= NT2 attention GEMM (A hi; B hi+lo; K-chunk 64) =====
// Tile order: m fastest (consecutive CTAs share the B strip)
template <int EP>
__global__ void __launch_bounds__(256, 2)
mma_gemmA(const fp16* __restrict__ Ah, long long lda,
          const fp16* __restrict__ Bh, const fp16* __restrict__ Bl,
          long long ldb,
          const float* __restrict__ bias,
          float* __restrict__ Cf, long long ldc,
          int M, int Mtiles, int KC) {
    constexpr unsigned STAGE = 3 * PL64;
    extern __shared__ char smc[];
    unsigned smbase;
    asm("{ .reg .u64 t; cvta.to.shared.u64 t, %1; cvt.u32.u64 %0, t; }"
        : "=r"(smbase) : "l"(smc));

    const int tid = threadIdx.x, wid = tid >> 5, lane = tid & 31;
    const int g = lane >> 2, tg = lane & 3;
    const int wm = wid >> 2, wn = wid & 3;
    const int mt = blockIdx.x % Mtiles, nt = blockIdx.x / Mtiles;
    const int n0 = nt * 128, m0 = mt * 128;

    const int s4 = lane >> 3, lr = lane & 7;
    const int aRowL = lr + (s4 & 1) * 8, aColL = (s4 >> 1) * 8;
    const int bRowL = lr + (s4 >> 1) * 8, bColL = (s4 & 1) * 8;

    float acc[4][4][4];
#pragma unroll
    for (int i = 0; i < 4; i++)
#pragma unroll
        for (int j = 0; j < 4; j++)
#pragma unroll
            for (int r = 0; r < 4; r++) acc[i][j][r] = 0.f;

    auto issue = [&](int c) {
        const int k0 = c * 64;
        unsigned sb = smbase + (c & 1) * STAGE;
#pragma unroll
        for (int i = 0; i < 4; i++) {
            int item = tid + i * 256;
            int row = item >> 3, c8 = item & 7;
            int m = m0 + row;
            int sz = (m < M) ? 16 : 0;
            size_t go = (size_t)(m < M ? m : 0) * lda + k0 + c8 * 8;
            cpa16(sb + row * 144 + c8 * 16, Ah + go, sz);
        }
#pragma unroll
        for (int i = 0; i < 4; i++) {
            int item = tid + i * 256;
            int row = item >> 3, c8 = item & 7;
            size_t go = (size_t)(n0 + row) * ldb + k0 + c8 * 8;
            unsigned so = sb + PL64 + row * 144 + c8 * 16;
            cpa16(so, Bh + go, 16);
            cpa16(so + PL64, Bl + go, 16);
        }
    };

    issue(0);
    CPA_COMMIT();

    for (int c = 0; c < KC; ++c) {
        if (c + 1 < KC) { issue(c + 1); CPA_COMMIT(); CPA_WAIT(1); }
        else            { CPA_WAIT(0); }
        __syncthreads();

        unsigned sb = smbase + (c & 1) * STAGE;
        unsigned sbB = sb + PL64;
#pragma unroll
        for (int ks = 0; ks < 4; ks++) {
            const int kb = ks * 16;
            unsigned bh_[4][2], bl_[4][2];
#pragma unroll
            for (int p = 0; p < 2; p++) {
                int rn0 = wn * 32 + p * 16;
                unsigned ba = sbB + (unsigned)((rn0 + bRowL) * STR64 + kb + bColL) * 2;
                LDSM4(bh_[2 * p][0], bh_[2 * p][1], bh_[2 * p + 1][0], bh_[2 * p + 1][1], ba);
                LDSM4(bl_[2 * p][0], bl_[2 * p][1], bl_[2 * p + 1][0], bl_[2 * p + 1][1],
                      ba + PL64);
            }
#pragma unroll
            for (int mi = 0; mi < 4; mi++) {
                int rm0 = wm * 64 + mi * 16;
                unsigned aa = sb + (unsigned)((rm0 + aRowL) * STR64 + kb + aColL) * 2;
                unsigned ah_[4];
                LDSM4(ah_[0], ah_[1], ah_[2], ah_[3], aa);
#pragma unroll
                for (int ni = 0; ni < 4; ni++) {
                    mma16816(acc[mi][ni], ah_, bh_[ni]);
                    mma16816(acc[mi][ni], ah_, bl_[ni]);
                }
            }
        }
        __syncthreads();
    }

    float* sOut = (float*)smc;
#pragma unroll
    for (int mi = 0; mi < 4; mi++) {
        int lrow = wm * 64 + mi * 16 + g;
#pragma unroll
        for (int ni = 0; ni < 4; ni++) {
            int j = wn * 32 + ni * 8 + tg * 2;
            float b0 = 0.f, b1 = 0.f;
            if (EP == 2) { b0 = bias[n0 + j]; b1 = bias[n0 + j + 1]; }
#pragma unroll
            for (int hh = 0; hh < 2; hh++) {
                float v0 = acc[mi][ni][hh * 2 + 0] + b0;
                float v1 = acc[mi][ni][hh * 2 + 1] + b1;
                *(float2*)&sOut[(lrow + hh * 8) * 132 + j] = make_float2(v0, v1);
            }
        }
    }
    __syncthreads();
#pragma unroll
    for (int i = 0; i < 16; i++) {
        int item = tid + i * 256;
        int row = item >> 5;
        int c4 = (item & 31) * 4;
        int m = m0 + row;
        if (m >= M) continue;
        float4 v = *(float4*)&sOut[row * 132 + c4];
        float* p = Cf + (size_t)m * ldc + n0 + c4;
        if (EP == 2) {
            float4 old = *(float4*)p;
            v.x += old.x; v.y += old.y; v.z += old.z; v.w += old.w;
        }
        *(float4*)p = v;
    }
}

// ======================= NT1 MoE GEMM (K-chunk 64, 2-stage, m-fast) =========
// EP: 3 = gelu(+bias) -> fp16 Ch; 4 = +bias -> fp16 Ch
template <int EP>
__global__ void __launch_bounds__(256, 2)
mma_gemm64(const fp16* __restrict__ Ah, long long lda, long long aExp,
           const fp16* __restrict__ Bh, long long ldb, long long bExp,
           const float* __restrict__ bias, long long biasExp,
           fp16* __restrict__ Ch, long long ldc, long long cExp,
           int M, int Mtiles, int KC) {
    constexpr unsigned STAGE = 2 * PL64;
    extern __shared__ char smc[];
    unsigned smbase;
    asm("{ .reg .u64 t; cvta.to.shared.u64 t, %1; cvt.u32.u64 %0, t; }"
        : "=r"(smbase) : "l"(smc));

    const int tid = threadIdx.x, wid = tid >> 5, lane = tid & 31;
    const int g = lane >> 2, tg = lane & 3;
    const int wm = wid >> 2, wn = wid & 3;
    const int e = blockIdx.y;
    const int mt = blockIdx.x % Mtiles, nt = blockIdx.x / Mtiles;
    const int n0 = nt * 128, m0 = mt * 128;

    const fp16* Abh = Ah + (size_t)e * aExp;
    const fp16* Bbh = Bh + (size_t)e * bExp;

    const int s4 = lane >> 3, lr = lane & 7;
    const int aRowL = lr + (s4 & 1) * 8, aColL = (s4 >> 1) * 8;
    const int bRowL = lr + (s4 >> 1) * 8, bColL = (s4 & 1) * 8;

    float acc[4][4][4];
#pragma unroll
    for (int i = 0; i < 4; i++)
#pragma unroll
        for (int j = 0; j < 4; j++)
#pragma unroll
            for (int r = 0; r < 4; r++) acc[i][j][r] = 0.f;

    auto issue = [&](int c) {
        const int k0 = c * 64;
        unsigned sb = smbase + (c & 1) * STAGE;
#pragma unroll
        for (int i = 0; i < 4; i++) {
            int item = tid + i * 256;
            int row = item >> 3, c8 = item & 7;
            int m = m0 + row;
            int sz = (m < M) ? 16 : 0;
            size_t go = (size_t)(m < M ? m : 0) * lda + k0 + c8 * 8;
            cpa16(sb + row * 144 + c8 * 16, Abh + go, sz);
        }
#pragma unroll
        for (int i = 0; i < 4; i++) {
            int item = tid + i * 256;
            int row = item >> 3, c8 = item & 7;
            size_t go = (size_t)(n0 + row) * ldb + k0 + c8 * 8;
            cpa16(sb + PL64 + row * 144 + c8 * 16, Bbh + go, 16);
        }
    };

    issue(0);
    CPA_COMMIT();

    for (int c = 0; c < KC; ++c) {
        if (c + 1 < KC) { issue(c + 1); CPA_COMMIT(); CPA_WAIT(1); }
        else            { CPA_WAIT(0); }
        __syncthreads();

        unsigned sb = smbase + (c & 1) * STAGE;
        unsigned sbB = sb + PL64;
#pragma unroll
        for (int ks = 0; ks < 4; ks++) {
            const int kb = ks * 16;
            unsigned bh_[4][2];
#pragma unroll
            for (int p = 0; p < 2; p++) {
                int rn0 = wn * 32 + p * 16;
                unsigned ba = sbB + (unsigned)((rn0 + bRowL) * STR64 + kb + bColL) * 2;
                LDSM4(bh_[2 * p][0], bh_[2 * p][1], bh_[2 * p + 1][0], bh_[2 * p + 1][1], ba);
            }
#pragma unroll
            for (int mi = 0; mi < 4; mi++) {
                int rm0 = wm * 64 + mi * 16;
                unsigned aa = sb + (unsigned)((rm0 + aRowL) * STR64 + kb + aColL) * 2;
                unsigned ah_[4];
                LDSM4(ah_[0], ah_[1], ah_[2], ah_[3], aa);
#pragma unroll
                for (int ni = 0; ni < 4; ni++)
                    mma16816(acc[mi][ni], ah_, bh_[ni]);
            }
        }
        __syncthreads();
    }

    float* sOut = (float*)smc;
#pragma unroll
    for (int mi = 0; mi < 4; mi++) {
        int lrow = wm * 64 + mi * 16 + g;
#pragma unroll
        for (int ni = 0; ni < 4; ni++) {
            int j = wn * 32 + ni * 8 + tg * 2;
            float b0 = bias[(size_t)e * biasExp + n0 + j];
            float b1 = bias[(size_t)e * biasExp + n0 + j + 1];
#pragma unroll
            for (int hh = 0; hh < 2; hh++) {
                float v0 = acc[mi][ni][hh * 2 + 0] + b0;
                float v1 = acc[mi][ni][hh * 2 + 1] + b1;
                if (EP == 3) { v0 = gelu_exact(v0); v1 = gelu_exact(v1); }
                *(float2*)&sOut[(lrow + hh * 8) * 132 + j] = make_float2(v0, v1);
            }
        }
    }
    __syncthreads();
#pragma unroll
    for (int i = 0; i < 8; i++) {
        int item = tid + i * 256;
        int row = item >> 4;
        int c8 = (item & 15) * 8;
        int m = m0 + row;
        if (m >= M) continue;
        float4 f0 = *(float4*)&sOut[row * 132 + c8];
        float4 f1 = *(float4*)&sOut[row * 132 + c8 + 4];
        __half2 h0 = __floats2half2_rn(f0.x, f0.y);
        __half2 h1 = __floats2half2_rn(f0.z, f0.w);
        __half2 h2 = __floats2half2_rn(f1.x, f1.y);
        __half2 h3 = __floats2half2_rn(f1.z, f1.w);
        uint4 u = make_uint4(*(unsigned*)&h0, *(unsigned*)&h1,
                             *(unsigned*)&h2, *(unsigned*)&h3);
        *(uint4*)(Ch + (size_t)e * cExp + (size_t)m * ldc + n0 + c8) = u;
    }
}

// ======================= transpose + split convert (64x64 tiles) ============
template <int LO>
__global__ void __launch_bounds__(256)
convT(const float* __restrict__ src, long long sExp, int K, int N,
      fp16* __restrict__ th, fp16* __restrict__ tl, long long tExp) {
    __shared__ float t[64][65];
    int e = blockIdx.z;
    int k0 = blockIdx.x * 64, nn0 = blockIdx.y * 64;
    const float* sp = src + (size_t)e * sExp;
    {
        int rrow = threadIdx.x >> 4;
        int c4 = (threadIdx.x & 15) * 4;
#pragma unroll
        for (int r = 0; r < 4; r++) {
            int k = rrow + r * 16;
            float4 v = *(const float4*)(sp + (size_t)(k0 + k) * N + nn0 + c4);
            t[k][c4 + 0] = v.x; t[k][c4 + 1] = v.y;
            t[k][c4 + 2] = v.z; t[k][c4 + 3] = v.w;
        }
    }
    __syncthreads();
    {
        int n = threadIdx.x >> 2;
        int kq = (threadIdx.x & 3) * 16;
        size_t o = (size_t)e * tExp + (size_t)(nn0 + n) * K + k0 + kq;
#pragma unroll
        for (int i = 0; i < 4; i++) {
            float v0 = t[kq + i * 4 + 0][n], v1 = t[kq + i * 4 + 1][n];
            float v2 = t[kq + i * 4 + 2][n], v3 = t[kq + i * 4 + 3][n];
            __half2 h0 = __floats2half2_rn(v0, v1);
            __half2 h1 = __floats2half2_rn(v2, v3);
            *(uint2*)(th + o + i * 4) = make_uint2(*(unsigned*)&h0, *(unsigned*)&h1);
            if (LO) {
                float2 r0 = __half22float2(h0), r1 = __half22float2(h1);
                __half2 l0 = __floats2half2_rn(v0 - r0.x, v1 - r0.y);
                __half2 l1 = __floats2half2_rn(v2 - r1.x, v3 - r1.y);
                *(uint2*)(tl + o + i * 4) = make_uint2(*(unsigned*)&l0, *(unsigned*)&l1);
            }
        }
    }
}

// ======================= gate_w transpose =======================
__global__ void gwT_kernel(const float* __restrict__ gw, float* __restrict__ gwT) {
    int i = blockIdx.x * blockDim.x + threadIdx.x;
    if (i >= NE * CDIM) return;
    int e = i / CDIM, c = i % CDIM;
    gwT[i] = gw[c * NE + e];
}

// ======================= pack Wq/Wk/Wv -> [3C][C] fp16 hi/lo =================
__global__ void pack_qkvT(const float* __restrict__ Wq,
                          const float* __restrict__ Wk,
                          const float* __restrict__ Wv,
                          fp16* __restrict__ th, fp16* __restrict__ tl) {
    int j = blockIdx.x;
    int which = j / CDIM, hs = j % CDIM;
    int h = hs / HSD, s = hs % HSD;
    const float* W = (which == 0) ? Wq : ((which == 1) ? Wk : Wv);
    for (int c = threadIdx.x; c < CDIM; c += 256) {
        float v = W[((size_t)h * CDIM + c) * HSD + s];
        fp16 hi = __float2half_rn(v);
        size_t o = (size_t)j * CDIM + c;
        th[o] = hi;
        tl[o] = __float2half_rn(v - __half2float(hi));
    }
}

// ======================= embedding =======================
__global__ void embed_kernel(const int* __restrict__ idx,
                             const float* __restrict__ tok,
                             const float* __restrict__ pos,
                             float* __restrict__ x) {
    int n = blockIdx.x;
    int t = n % TSEQ;
    int v = idx[n];
    for (int c = threadIdx.x; c < CDIM; c += blockDim.x)
        x[n * CDIM + c] = tok[v * CDIM + c] + pos[t * CDIM + c];
}

// ======================= layernorm =======================
__global__ void ln_kernel(const float* __restrict__ x,
                          const float* __restrict__ g,
                          const float* __restrict__ b,
                          float* __restrict__ out,
                          fp16* __restrict__ oh) {
    int n = blockIdx.x;
    int tid = threadIdx.x;
    __shared__ float s1[256], s2[256];
    const float* xr = x + (size_t)n * CDIM;
    float a = 0.f, q = 0.f;
    for (int c = tid; c < CDIM; c += 256) { float v = xr[c]; a += v; q += v * v; }
    s1[tid] = a; s2[tid] = q;
    __syncthreads();
    for (int s = 128; s > 0; s >>= 1) {
        if (tid < s) { s1[tid] += s1[tid + s]; s2[tid] += s2[tid + s]; }
        __syncthreads();
    }
    float mean = s1[0] * (1.f / CDIM);
    float var  = s2[0] * (1.f / CDIM) - mean * mean;
    float r = rsqrtf(var + 1e-5f);
    for (int c = tid; c < CDIM; c += 256) {
        float o = (xr[c] - mean) * r * g[c] + b[c];
        size_t p = (size_t)n * CDIM + c;
        out[p] = o;
        oh[p] = __float2half_rn(o);
    }
}

// ======================= attention v2 (AV unrolled) =======================
#define KV_STR 25
#define ATTN_SMEM ((TSEQ * KV_STR * 2 + 8 * 424 + 8 * 24) * 4)

__global__ void __launch_bounds__(256)
attn2_kernel(const float* __restrict__ qkv, fp16* __restrict__ atth) {
    int h = blockIdx.x, b = blockIdx.y;
    extern __shared__ float sm[];
    float* Ks = sm;
    float* Vs = Ks + TSEQ * KV_STR;
    float* sc = Vs + TSEQ * KV_STR;
    float* qb = sc + 8 * 424;

    int tid = threadIdx.x, wid = tid >> 5, lane = tid & 31;
    int n0 = b * TSEQ;

    for (int i = tid; i < TSEQ * HSD; i += 256) {
        int u = i / HSD, s = i - u * HSD;
        const float* base = qkv + (size_t)(n0 + u) * (3 * CDIM) + h * HSD + s;
        Ks[u * KV_STR + s] = base[CDIM];
        Vs[u * KV_STR + s] = base[2 * CDIM];
    }
    __syncthreads();

    const float scale = 0.20412414523193154f;
    float* scw = sc + wid * 424;
    float* qw  = qb + wid * 24;

    for (int t = wid; t < TSEQ; t += 8) {
        if (lane < HSD)
            qw[lane] = qkv[(size_t)(n0 + t) * (3 * CDIM) + h * HSD + lane];
        __syncwarp();

        float lmax = -1e30f;
        for (int u = lane; u <= t; u += 32) {
            const float* kr = Ks + u * KV_STR;
            float d = 0.f;
#pragma unroll
            for (int s = 0; s < HSD; s++) d += qw[s] * kr[s];
            d *= scale;
            scw[u] = d;
            lmax = fmaxf(lmax, d);
        }
        for (int o = 16; o > 0; o >>= 1)
            lmax = fmaxf(lmax, __shfl_xor_sync(0xFFFFFFFFu, lmax, o));

        float lsum = 0.f;
        for (int u = lane; u <= t; u += 32) {
            float ev = expf(scw[u] - lmax);
            scw[u] = ev;
            lsum += ev;
        }
        for (int o = 16; o > 0; o >>= 1)
            lsum += __shfl_xor_sync(0xFFFFFFFFu, lsum, o);
        float inv = 1.f / lsum;
        __syncwarp();

        if (lane < HSD) {
            float a0 = 0.f, a1 = 0.f, a2 = 0.f, a3 = 0.f;
            int u = 0;
            for (; u + 4 <= t + 1; u += 4) {
                a0 += scw[u + 0] * Vs[(u + 0) * KV_STR + lane];
                a1 += scw[u + 1] * Vs[(u + 1) * KV_STR + lane];
                a2 += scw[u + 2] * Vs[(u + 2) * KV_STR + lane];
                a3 += scw[u + 3] * Vs[(u + 3) * KV_STR + lane];
            }
            for (; u <= t; u++) a0 += scw[u] * Vs[u * KV_STR + lane];
            float a = ((a0 + a1) + (a2 + a3)) * inv;
            atth[(size_t)(n0 + t) * CDIM + h * HSD + lane] = __float2half_rn(a);
        }
        __syncwarp();
    }
}

// ======================= gate softmax v2 =======================
__global__ void __launch_bounds__(256)
gate2_kernel(const float* __restrict__ h2, const float* __restrict__ gwT,
             const float* __restrict__ gb, float* __restrict__ gates) {
    int n = blockIdx.x;
    int tid = threadIdx.x, wid = tid >> 5, lane = tid & 31;
    __shared__ float lg[NE];
    __shared__ float hsm[CDIM];
    for (int c = tid; c < CDIM; c += 256) hsm[c] = h2[(size_t)n * CDIM + c];
    __syncthreads();
    for (int e = wid; e < NE; e += 8) {
        const float* w = gwT + (size_t)e * CDIM;
        float a = 0.f;
        for (int c = lane; c < CDIM; c += 32) a += hsm[c] * w[c];
        for (int o = 16; o > 0; o >>= 1) a += __shfl_xor_sync(0xFFFFFFFFu, a, o);
        if (lane == 0) lg[e] = a + gb[e];
    }
    __syncthreads();
    if (tid < 32) {
        float v = lg[tid];
        float mx = v;
        for (int o = 16; o > 0; o >>= 1) mx = fmaxf(mx, __shfl_xor_sync(0xFFFFFFFFu, mx, o));
        float ex = expf(v - mx);
        float smv = ex;
        for (int o = 16; o > 0; o >>= 1) smv += __shfl_xor_sync(0xFFFFFFFFu, smv, o);
        gates[n * NE + tid] = ex / smv;
    }
}

// ======================= MoE combine (fp16 eo) =======================
__global__ void combine_kernel(const fp16* __restrict__ eo,
                               const float* __restrict__ gates,
                               float* __restrict__ x) {
    int n = blockIdx.x;
    __shared__ float gs[NE];
    if (threadIdx.x < NE) gs[threadIdx.x] = gates[n * NE + threadIdx.x];
    __syncthreads();
    for (int c = threadIdx.x; c < CDIM; c += blockDim.x) {
        float a = 0.f;
        const fp16* er = eo + (size_t)n * (NE * CDIM) + c;
#pragma unroll 8
        for (int e = 0; e < NE; e++) a += gs[e] * __half2float(er[e * CDIM]);
        x[(size_t)n * CDIM + c] += a;
    }
}

// ======================= scalar SGEMM (lm head only) =======================
__global__ void __launch_bounds__(256)
lm_head_kernel(const float* __restrict__ A, const float* __restrict__ B,
               const float* __restrict__ bias, float* __restrict__ C,
               int M, int N, int K) {
    __shared__ float As[64][17];
    __shared__ float Bs[16][64];
    int tid = threadIdx.x;
    int jTile = blockIdx.x * 64;
    int mTile = blockIdx.y * 64;
    int tx = tid & 15, ty = tid >> 4;

    float acc[4][4];
#pragma unroll
    for (int r = 0; r < 4; r++)
#pragma unroll
        for (int c = 0; c < 4; c++) acc[r][c] = 0.f;

    int aRow = tid >> 2, aK = (tid & 3) * 4;
    int bJ = tid & 63, bK0 = tid >> 6;

    for (int k0 = 0; k0 < K; k0 += 16) {
        int m = mTile + aRow;
        if (m < M) {
            float4 av = *(const float4*)(A + (size_t)m * K + k0 + aK);
            As[aRow][aK + 0] = av.x; As[aRow][aK + 1] = av.y;
            As[aRow][aK + 2] = av.z; As[aRow][aK + 3] = av.w;
        } else {
            As[aRow][aK + 0] = 0.f; As[aRow][aK + 1] = 0.f;
            As[aRow][aK + 2] = 0.f; As[aRow][aK + 3] = 0.f;
        }
#pragma unroll
        for (int i = 0; i < 4; i++) {
            int kk = bK0 + i * 4;
            Bs[kk][bJ] = (jTile + bJ < N)
                ? B[(size_t)(k0 + kk) * N + jTile + bJ] : 0.f;
        }
        __syncthreads();
#pragma unroll
        for (int k = 0; k < 16; k++) {
            float4 bv = *(const float4*)&Bs[k][tx * 4];
            float a0 = As[ty * 4 + 0][k], a1 = As[ty * 4 + 1][k];
            float a2 = As[ty * 4 + 2][k], a3 = As[ty * 4 + 3][k];
            acc[0][0] += a0 * bv.x; acc[0][1] += a0 * bv.y; acc[0][2] += a0 * bv.z; acc[0][3] += a0 * bv.w;
            acc[1][0] += a1 * bv.x; acc[1][1] += a1 * bv.y; acc[1][2] += a1 * bv.z; acc[1][3] += a1 * bv.w;
            acc[2][0] += a2 * bv.x; acc[2][1] += a2 * bv.y; acc[2][2] += a2 * bv.z; acc[2][3] += a2 * bv.w;
            acc[3][0] += a3 * bv.x; acc[3][1] += a3 * bv.y; acc[3][2] += a3 * bv.z; acc[3][3] += a3 * bv.w;
        }
        __syncthreads();
    }
#pragma unroll
    for (int r = 0; r < 4; r++) {
        int m = mTile + ty * 4 + r;
        if (m >= M) continue;
#pragma unroll
        for (int c = 0; c < 4; c++) {
            int j = jTile + tx * 4 + c;
            if (j >= N) continue;
            C[(size_t)m * N + j] = acc[r][c] + bias[j];
        }
    }
}

// ======================= launch =======================
extern "C" void kernel_launch(void* const* d_in, const int* in_sizes, int n_in,
                              void* d_out, int out_size) {
    const int*   idx    = (const int*)  d_in[0];
    const float* tok    = (const float*)d_in[1];
    const float* pos    = (const float*)d_in[2];
    const float* ln1_g  = (const float*)d_in[3];
    const float* ln1_b  = (const float*)d_in[4];
    const float* Wq     = (const float*)d_in[5];
    const float* Wk     = (const float*)d_in[6];
    const float* Wv     = (const float*)d_in[7];
    const float* Wo     = (const float*)d_in[8];
    const float* bo     = (const float*)d_in[9];
    const float* ln2_g  = (const float*)d_in[10];
    const float* ln2_b  = (const float*)d_in[11];
    const float* gate_w = (const float*)d_in[12];
    const float* gate_b = (const float*)d_in[13];
    const float* W1     = (const float*)d_in[14];
    const float* b1     = (const float*)d_in[15];
    const float* W2     = (const float*)d_in[16];
    const float* b2     = (const float*)d_in[17];
    const float* lnf_g  = (const float*)d_in[18];
    const float* lnf_b  = (const float*)d_in[19];
    const float* lm_w   = (const float*)d_in[20];
    const float* lm_b   = (const float*)d_in[21];
    float* out = (float*)d_out;

    float *x, *h, *qkv, *gates, *gwT;
    fp16 *eo, *hh, *atth, *wpth, *wptl, *woth, *wotl;
    fp16 *w1th, *w2th, *hidh;
    cudaGetSymbolAddress((void**)&x,     g_x);
    cudaGetSymbolAddress((void**)&h,     g_h);
    cudaGetSymbolAddress((void**)&qkv,   g_qkv);
    cudaGetSymbolAddress((void**)&gates, g_gates);
    cudaGetSymbolAddress((void**)&gwT,   g_gwT);
    cudaGetSymbolAddress((void**)&eo,    g_eo);
    cudaGetSymbolAddress((void**)&hh,    g_hh);
    cudaGetSymbolAddress((void**)&atth,  g_atth);
    cudaGetSymbolAddress((void**)&wpth,  g_wpth);
    cudaGetSymbolAddress((void**)&wptl,  g_wptl);
    cudaGetSymbolAddress((void**)&woth,  g_woth);
    cudaGetSymbolAddress((void**)&wotl,  g_wotl);
    cudaGetSymbolAddress((void**)&w1th,  g_w1th);
    cudaGetSymbolAddress((void**)&w2th,  g_w2th);
    cudaGetSymbolAddress((void**)&hidh,  g_hidh);

    cudaFuncSetAttribute(mma_gemmA<0>, cudaFuncAttributeMaxDynamicSharedMemorySize, SMEM_3PL);
    cudaFuncSetAttribute(mma_gemmA<2>, cudaFuncAttributeMaxDynamicSharedMemorySize, SMEM_3PL);
    cudaFuncSetAttribute(mma_gemm64<3>, cudaFuncAttributeMaxDynamicSharedMemorySize, SMEM_2PL);
    cudaFuncSetAttribute(mma_gemm64<4>, cudaFuncAttributeMaxDynamicSharedMemorySize, SMEM_2PL);
    cudaFuncSetAttribute(attn2_kernel, cudaFuncAttributeMaxDynamicSharedMemorySize, ATTN_SMEM);

    const int MT = (NTOK + 127) / 128;   // 7

    // ---- pre-convert weights ----
    for (int l = 0; l < NL; l++) {
        convT<0><<<dim3(CDIM / 64, F4D / 64, NE), 256>>>(
            W1 + (size_t)l * NE * CDIM * F4D, (long long)CDIM * F4D, CDIM, F4D,
            w1th + (size_t)l * NE * F4D * CDIM, nullptr,
            (long long)F4D * CDIM);
        convT<0><<<dim3(F4D / 64, CDIM / 64, NE), 256>>>(
            W2 + (size_t)l * NE * F4D * CDIM, (long long)F4D * CDIM, F4D, CDIM,
            w2th + (size_t)l * NE * CDIM * F4D, nullptr,
            (long long)CDIM * F4D);
        convT<1><<<dim3(CDIM / 64, CDIM / 64, 1), 256>>>(
            Wo + (size_t)l * CDIM * CDIM, 0, CDIM, CDIM,
            woth + (size_t)l * CDIM * CDIM, wotl + (size_t)l * CDIM * CDIM, 0);
    }

    embed_kernel<<<NTOK, 256>>>(idx, tok, pos, x);

    for (int l = 0; l < NL; l++) {
        // --- attention ---
        ln_kernel<<<NTOK, 256>>>(x, ln1_g + l * CDIM, ln1_b + l * CDIM, h, hh);
        pack_qkvT<<<3 * CDIM, 256>>>(
            Wq + (size_t)l * NH * CDIM * HSD,
            Wk + (size_t)l * NH * CDIM * HSD,
            Wv + (size_t)l * NH * CDIM * HSD, wpth, wptl);
        mma_gemmA<0><<<dim3(MT * 18), 256, SMEM_3PL>>>(
            hh, CDIM, wpth, wptl, CDIM, nullptr,
            qkv, 3 * CDIM, NTOK, MT, CDIM / 64);
        attn2_kernel<<<dim3(NH, BSZ), 256, ATTN_SMEM>>>(qkv, atth);
        mma_gemmA<2><<<dim3(MT * 6), 256, SMEM_3PL>>>(
            atth, CDIM,
            woth + (size_t)l * CDIM * CDIM, wotl + (size_t)l * CDIM * CDIM, CDIM,
            bo + l * CDIM, x, CDIM, NTOK, MT, CDIM / 64);

        // --- MoE ---
        ln_kernel<<<NTOK, 256>>>(x, ln2_g + l * CDIM, ln2_b + l * CDIM, h, hh);
        gwT_kernel<<<(NE * CDIM + 255) / 256, 256>>>(
            gate_w + (size_t)l * CDIM * NE, gwT);
        gate2_kernel<<<NTOK, 256>>>(h, gwT, gate_b + l * NE, gates);
        mma_gemm64<3><<<dim3(MT * (F4D / 128), NE), 256, SMEM_2PL>>>(
            hh, CDIM, 0,
            w1th + (size_t)l * NE * F4D * CDIM, CDIM, (long long)F4D * CDIM,
            b1 + (size_t)l * NE * F4D, F4D,
            hidh, (long long)NE * F4D, F4D,
            NTOK, MT, CDIM / 64);
        mma_gemm64<4><<<dim3(MT * (CDIM / 128), NE), 256, SMEM_2PL>>>(
            hidh, (long long)NE * F4D, F4D,
            w2th + (size_t)l * NE * CDIM * F4D, F4D, (long long)CDIM * F4D,
            b2 + (size_t)l * NE * CDIM, CDIM,
            eo, (long long)NE * CDIM, CDIM,
            NTOK, MT, F4D / 64);
        combine_kernel<<<NTOK, 256>>>(eo, gates, x);
    }

    // --- final LN + lm head ---
    ln_kernel<<<NTOK, 256>>>(x, lnf_g, lnf_b, h, hh);
    lm_head_kernel<<<dim3((NV + 63) / 64, (NTOK + 63) / 64), 256>>>(
        h, lm_w, lm_b, out, NTOK, NV, CDIM);
}

// round 17
// speedup vs baseline: 1.4013x; 1.0646x over previous
#include <cuda_runtime.h>
#include <cuda_fp16.h>
#include <math.h>
#include <stdint.h>

// ---- problem constants ----
#define NTOK 844      // B*T = 2*422
#define TSEQ 422
#define BSZ  2
#define CDIM 768
#define NH   32
#define HSD  24
#define NE   32
#define F4D  3072
#define NL   2
#define NV   100

typedef __half fp16;

// ---- device scratch ----
__device__ float g_x  [NTOK * CDIM];
__device__ float g_h  [NTOK * CDIM];
__device__ float g_qkv[NTOK * 3 * CDIM];
__device__ float g_gates[NTOK * NE];
__device__ float g_gwT[NE * CDIM];

__device__ fp16 g_eo [(size_t)NTOK * NE * CDIM];
__device__ fp16 g_hh [NTOK * CDIM];
__device__ fp16 g_atth[NTOK * CDIM];
__device__ fp16 g_wpth[3 * CDIM * CDIM], g_wptl[3 * CDIM * CDIM];
__device__ fp16 g_woth[NL * CDIM * CDIM], g_wotl[NL * CDIM * CDIM];
__device__ fp16 g_w1th[(size_t)NL * NE * F4D * CDIM];
__device__ fp16 g_w2th[(size_t)NL * NE * CDIM * F4D];
__device__ fp16 g_hidh[(size_t)NTOK * NE * F4D];

// ======================= helpers =======================
__device__ __forceinline__ float gelu_exact(float v) {
    return 0.5f * v * (1.f + erff(v * 0.70710678118654752f));
}

__device__ __forceinline__ void mma16816(float* d, const unsigned* a, const unsigned* b) {
    asm volatile(
        "mma.sync.aligned.m16n8k16.row.col.f32.f16.f16.f32 "
        "{%0,%1,%2,%3}, {%4,%5,%6,%7}, {%8,%9}, {%0,%1,%2,%3};"
        : "+f"(d[0]), "+f"(d[1]), "+f"(d[2]), "+f"(d[3])
        : "r"(a[0]), "r"(a[1]), "r"(a[2]), "r"(a[3]), "r"(b[0]), "r"(b[1]));
}

__device__ __forceinline__ void cpa16(unsigned s, const void* g, int sz) {
    asm volatile("cp.async.cg.shared.global [%0], [%1], 16, %2;"
                 :: "r"(s), "l"(g), "r"(sz));
}
#define CPA_COMMIT() asm volatile("cp.async.commit_group;" ::: "memory")
#define CPA_WAIT(n)  asm volatile("cp.async.wait_group %0;" :: "n"(n) : "memory")

#define LDSM4(r0, r1, r2, r3, addr)                                            \
    asm volatile("ldmatrix.sync.aligned.m8n8.x4.shared.b16 {%0,%1,%2,%3}, [%4];" \
        : "=r"(r0), "=r"(r1), "=r"(r2), "=r"(r3) : "r"(addr))

// ======================= shared GEMM geometry =======================
#define STR64 72
#define PL64 (128 * 144)
#define SMEM_3PL 110592            // attn NT2: 2 stages * 3 planes
#define SMEM_2PL  73728            // MoE NT1: 2 stages * 2 planes

// ======================= NT2 attention GEMM (A hi; B hi+lo; K-chunk 64) =====
// Tile order: m fastest (consecutive CTAs share the B strip)
template <int EP>
__global__ void __launch_bounds__(256, 2)
mma_gemmA(const fp16* __restrict__ Ah, long long lda,
          const fp16* __restrict__ Bh, const fp16* __restrict__ Bl,
          long long ldb,
          const float* __restrict__ bias,
          float* __restrict__ Cf, long long ldc,
          int M, int Mtiles, int KC) {
    constexpr unsigned STAGE = 3 * PL64;
    extern __shared__ char smc[];
    unsigned smbase;
    asm("{ .reg .u64 t; cvta.to.shared.u64 t, %1; cvt.u32.u64 %0, t; }"
        : "=r"(smbase) : "l"(smc));

    const int tid = threadIdx.x, wid = tid >> 5, lane = tid & 31;
    const int g = lane >> 2, tg = lane & 3;
    const int wm = wid >> 2, wn = wid & 3;
    const int mt = blockIdx.x % Mtiles, nt = blockIdx.x / Mtiles;
    const int n0 = nt * 128, m0 = mt * 128;

    const int s4 = lane >> 3, lr = lane & 7;
    const int aRowL = lr + (s4 & 1) * 8, aColL = (s4 >> 1) * 8;
    const int bRowL = lr + (s4 >> 1) * 8, bColL = (s4 & 1) * 8;

    float acc[4][4][4];
#pragma unroll
    for (int i = 0; i < 4; i++)
#pragma unroll
        for (int j = 0; j < 4; j++)
#pragma unroll
            for (int r = 0; r < 4; r++) acc[i][j][r] = 0.f;

    auto issue = [&](int c) {
        const int k0 = c * 64;
        unsigned sb = smbase + (c & 1) * STAGE;
#pragma unroll
        for (int i = 0; i < 4; i++) {
            int item = tid + i * 256;
            int row = item >> 3, c8 = item & 7;
            int m = m0 + row;
            int sz = (m < M) ? 16 : 0;
            size_t go = (size_t)(m < M ? m : 0) * lda + k0 + c8 * 8;
            cpa16(sb + row * 144 + c8 * 16, Ah + go, sz);
        }
#pragma unroll
        for (int i = 0; i < 4; i++) {
            int item = tid + i * 256;
            int row = item >> 3, c8 = item & 7;
            size_t go = (size_t)(n0 + row) * ldb + k0 + c8 * 8;
            unsigned so = sb + PL64 + row * 144 + c8 * 16;
            cpa16(so, Bh + go, 16);
            cpa16(so + PL64, Bl + go, 16);
        }
    };

    issue(0);
    CPA_COMMIT();

    for (int c = 0; c < KC; ++c) {
        if (c + 1 < KC) { issue(c + 1); CPA_COMMIT(); CPA_WAIT(1); }
        else            { CPA_WAIT(0); }
        __syncthreads();

        unsigned sb = smbase + (c & 1) * STAGE;
        unsigned sbB = sb + PL64;
#pragma unroll
        for (int ks = 0; ks < 4; ks++) {
            const int kb = ks * 16;
            unsigned bh_[4][2], bl_[4][2];
#pragma unroll
            for (int p = 0; p < 2; p++) {
                int rn0 = wn * 32 + p * 16;
                unsigned ba = sbB + (unsigned)((rn0 + bRowL) * STR64 + kb + bColL) * 2;
                LDSM4(bh_[2 * p][0], bh_[2 * p][1], bh_[2 * p + 1][0], bh_[2 * p + 1][1], ba);
                LDSM4(bl_[2 * p][0], bl_[2 * p][1], bl_[2 * p + 1][0], bl_[2 * p + 1][1],
                      ba + PL64);
            }
#pragma unroll
            for (int mi = 0; mi < 4; mi++) {
                int rm0 = wm * 64 + mi * 16;
                unsigned aa = sb + (unsigned)((rm0 + aRowL) * STR64 + kb + aColL) * 2;
                unsigned ah_[4];
                LDSM4(ah_[0], ah_[1], ah_[2], ah_[3], aa);
#pragma unroll
                for (int ni = 0; ni < 4; ni++) {
                    mma16816(acc[mi][ni], ah_, bh_[ni]);
                    mma16816(acc[mi][ni], ah_, bl_[ni]);
                }
            }
        }
        __syncthreads();
    }

    float* sOut = (float*)smc;
#pragma unroll
    for (int mi = 0; mi < 4; mi++) {
        int lrow = wm * 64 + mi * 16 + g;
#pragma unroll
        for (int ni = 0; ni < 4; ni++) {
            int j = wn * 32 + ni * 8 + tg * 2;
            float b0 = 0.f, b1 = 0.f;
            if (EP == 2) { b0 = bias[n0 + j]; b1 = bias[n0 + j + 1]; }
#pragma unroll
            for (int hh = 0; hh < 2; hh++) {
                float v0 = acc[mi][ni][hh * 2 + 0] + b0;
                float v1 = acc[mi][ni][hh * 2 + 1] + b1;
                *(float2*)&sOut[(lrow + hh * 8) * 132 + j] = make_float2(v0, v1);
            }
        }
    }
    __syncthreads();
#pragma unroll
    for (int i = 0; i < 16; i++) {
        int item = tid + i * 256;
        int row = item >> 5;
        int c4 = (item & 31) * 4;
        int m = m0 + row;
        if (m >= M) continue;
        float4 v = *(float4*)&sOut[row * 132 + c4];
        float* p = Cf + (size_t)m * ldc + n0 + c4;
        if (EP == 2) {
            float4 old = *(float4*)p;
            v.x += old.x; v.y += old.y; v.z += old.z; v.w += old.w;
        }
        *(float4*)p = v;
    }
}

// ======================= NT1 MoE GEMM (K-chunk 64, 2-stage, m-fast) =========
// EP: 3 = gelu(+bias) -> fp16 Ch; 4 = +bias -> fp16 Ch
template <int EP>
__global__ void __launch_bounds__(256, 2)
mma_gemm64(const fp16* __restrict__ Ah, long long lda, long long aExp,
           const fp16* __restrict__ Bh, long long ldb, long long bExp,
           const float* __restrict__ bias, long long biasExp,
           fp16* __restrict__ Ch, long long ldc, long long cExp,
           int M, int Mtiles, int KC) {
    constexpr unsigned STAGE = 2 * PL64;
    extern __shared__ char smc[];
    unsigned smbase;
    asm("{ .reg .u64 t; cvta.to.shared.u64 t, %1; cvt.u32.u64 %0, t; }"
        : "=r"(smbase) : "l"(smc));

    const int tid = threadIdx.x, wid = tid >> 5, lane = tid & 31;
    const int g = lane >> 2, tg = lane & 3;
    const int wm = wid >> 2, wn = wid & 3;
    const int e = blockIdx.y;
    const int mt = blockIdx.x % Mtiles, nt = blockIdx.x / Mtiles;
    const int n0 = nt * 128, m0 = mt * 128;

    const fp16* Abh = Ah + (size_t)e * aExp;
    const fp16* Bbh = Bh + (size_t)e * bExp;

    const int s4 = lane >> 3, lr = lane & 7;
    const int aRowL = lr + (s4 & 1) * 8, aColL = (s4 >> 1) * 8;
    const int bRowL = lr + (s4 >> 1) * 8, bColL = (s4 & 1) * 8;

    float acc[4][4][4];
#pragma unroll
    for (int i = 0; i < 4; i++)
#pragma unroll
        for (int j = 0; j < 4; j++)
#pragma unroll
            for (int r = 0; r < 4; r++) acc[i][j][r] = 0.f;

    auto issue = [&](int c) {
        const int k0 = c * 64;
        unsigned sb = smbase + (c & 1) * STAGE;
#pragma unroll
        for (int i = 0; i < 4; i++) {
            int item = tid + i * 256;
            int row = item >> 3, c8 = item & 7;
            int m = m0 + row;
            int sz = (m < M) ? 16 : 0;
            size_t go = (size_t)(m < M ? m : 0) * lda + k0 + c8 * 8;
            cpa16(sb + row * 144 + c8 * 16, Abh + go, sz);
        }
#pragma unroll
        for (int i = 0; i < 4; i++) {
            int item = tid + i * 256;
            int row = item >> 3, c8 = item & 7;
            size_t go = (size_t)(n0 + row) * ldb + k0 + c8 * 8;
            cpa16(sb + PL64 + row * 144 + c8 * 16, Bbh + go, 16);
        }
    };

    issue(0);
    CPA_COMMIT();

    for (int c = 0; c < KC; ++c) {
        if (c + 1 < KC) { issue(c + 1); CPA_COMMIT(); CPA_WAIT(1); }
        else            { CPA_WAIT(0); }
        __syncthreads();

        unsigned sb = smbase + (c & 1) * STAGE;
        unsigned sbB = sb + PL64;
#pragma unroll
        for (int ks = 0; ks < 4; ks++) {
            const int kb = ks * 16;
            unsigned bh_[4][2];
#pragma unroll
            for (int p = 0; p < 2; p++) {
                int rn0 = wn * 32 + p * 16;
                unsigned ba = sbB + (unsigned)((rn0 + bRowL) * STR64 + kb + bColL) * 2;
                LDSM4(bh_[2 * p][0], bh_[2 * p][1], bh_[2 * p + 1][0], bh_[2 * p + 1][1], ba);
            }
#pragma unroll
            for (int mi = 0; mi < 4; mi++) {
                int rm0 = wm * 64 + mi * 16;
                unsigned aa = sb + (unsigned)((rm0 + aRowL) * STR64 + kb + aColL) * 2;
                unsigned ah_[4];
                LDSM4(ah_[0], ah_[1], ah_[2], ah_[3], aa);
#pragma unroll
                for (int ni = 0; ni < 4; ni++)
                    mma16816(acc[mi][ni], ah_, bh_[ni]);
            }
        }
        __syncthreads();
    }

    float* sOut = (float*)smc;
#pragma unroll
    for (int mi = 0; mi < 4; mi++) {
        int lrow = wm * 64 + mi * 16 + g;
#pragma unroll
        for (int ni = 0; ni < 4; ni++) {
            int j = wn * 32 + ni * 8 + tg * 2;
            float b0 = bias[(size_t)e * biasExp + n0 + j];
            float b1 = bias[(size_t)e * biasExp + n0 + j + 1];
#pragma unroll
            for (int hh = 0; hh < 2; hh++) {
                float v0 = acc[mi][ni][hh * 2 + 0] + b0;
                float v1 = acc[mi][ni][hh * 2 + 1] + b1;
                if (EP == 3) { v0 = gelu_exact(v0); v1 = gelu_exact(v1); }
                *(float2*)&sOut[(lrow + hh * 8) * 132 + j] = make_float2(v0, v1);
            }
        }
    }
    __syncthreads();
#pragma unroll
    for (int i = 0; i < 8; i++) {
        int item = tid + i * 256;
        int row = item >> 4;
        int c8 = (item & 15) * 8;
        int m = m0 + row;
        if (m >= M) continue;
        float4 f0 = *(float4*)&sOut[row * 132 + c8];
        float4 f1 = *(float4*)&sOut[row * 132 + c8 + 4];
        __half2 h0 = __floats2half2_rn(f0.x, f0.y);
        __half2 h1 = __floats2half2_rn(f0.z, f0.w);
        __half2 h2 = __floats2half2_rn(f1.x, f1.y);
        __half2 h3 = __floats2half2_rn(f1.z, f1.w);
        uint4 u = make_uint4(*(unsigned*)&h0, *(unsigned*)&h1,
                             *(unsigned*)&h2, *(unsigned*)&h3);
        *(uint4*)(Ch + (size_t)e * cExp + (size_t)m * ldc + n0 + c8) = u;
    }
}

// ======================= transpose + split convert (64x64 tiles) ============
template <int LO>
__global__ void __launch_bounds__(256)
convT(const float* __restrict__ src, long long sExp, int K, int N,
      fp16* __restrict__ th, fp16* __restrict__ tl, long long tExp) {
    __shared__ float t[64][65];
    int e = blockIdx.z;
    int k0 = blockIdx.x * 64, nn0 = blockIdx.y * 64;
    const float* sp = src + (size_t)e * sExp;
    {
        int rrow = threadIdx.x >> 4;
        int c4 = (threadIdx.x & 15) * 4;
#pragma unroll
        for (int r = 0; r < 4; r++) {
            int k = rrow + r * 16;
            float4 v = *(const float4*)(sp + (size_t)(k0 + k) * N + nn0 + c4);
            t[k][c4 + 0] = v.x; t[k][c4 + 1] = v.y;
            t[k][c4 + 2] = v.z; t[k][c4 + 3] = v.w;
        }
    }
    __syncthreads();
    {
        int n = threadIdx.x >> 2;
        int kq = (threadIdx.x & 3) * 16;
        size_t o = (size_t)e * tExp + (size_t)(nn0 + n) * K + k0 + kq;
#pragma unroll
        for (int i = 0; i < 4; i++) {
            float v0 = t[kq + i * 4 + 0][n], v1 = t[kq + i * 4 + 1][n];
            float v2 = t[kq + i * 4 + 2][n], v3 = t[kq + i * 4 + 3][n];
            __half2 h0 = __floats2half2_rn(v0, v1);
            __half2 h1 = __floats2half2_rn(v2, v3);
            *(uint2*)(th + o + i * 4) = make_uint2(*(unsigned*)&h0, *(unsigned*)&h1);
            if (LO) {
                float2 r0 = __half22float2(h0), r1 = __half22float2(h1);
                __half2 l0 = __floats2half2_rn(v0 - r0.x, v1 - r0.y);
                __half2 l1 = __floats2half2_rn(v2 - r1.x, v3 - r1.y);
                *(uint2*)(tl + o + i * 4) = make_uint2(*(unsigned*)&l0, *(unsigned*)&l1);
            }
        }
    }
}

// ======================= gate_w transpose =======================
__global__ void gwT_kernel(const float* __restrict__ gw, float* __restrict__ gwT) {
    int i = blockIdx.x * blockDim.x + threadIdx.x;
    if (i >= NE * CDIM) return;
    int e = i / CDIM, c = i % CDIM;
    gwT[i] = gw[c * NE + e];
}

// ======================= pack Wq/Wk/Wv v2 (coalesced) =======================
// For fixed h, W[h] is a contiguous [C][HS] block. Stage 256-c tiles through
// smem, emit 24 contiguous rows of th/tl.
__global__ void __launch_bounds__(256)
pack_qkvT2(const float* __restrict__ Wq, const float* __restrict__ Wk,
           const float* __restrict__ Wv,
           fp16* __restrict__ th, fp16* __restrict__ tl) {
    int h = blockIdx.x, which = blockIdx.y;
    const float* W = (which == 0) ? Wq : ((which == 1) ? Wk : Wv);
    const float* src = W + (size_t)h * CDIM * HSD;
    __shared__ float t[256][25];
    int tid = threadIdx.x;
    for (int c0 = 0; c0 < CDIM; c0 += 256) {
        for (int i = tid; i < 256 * HSD; i += 256) {
            int c = i / HSD, s = i - c * HSD;
            t[c][s] = src[c0 * HSD + i];
        }
        __syncthreads();
#pragma unroll 4
        for (int s = 0; s < HSD; s++) {
            float v = t[tid][s];
            fp16 hi = __float2half_rn(v);
            size_t o = (size_t)(which * CDIM + h * HSD + s) * CDIM + c0 + tid;
            th[o] = hi;
            tl[o] = __float2half_rn(v - __half2float(hi));
        }
        __syncthreads();
    }
}

// ======================= embedding =======================
__global__ void embed_kernel(const int* __restrict__ idx,
                             const float* __restrict__ tok,
                             const float* __restrict__ pos,
                             float* __restrict__ x) {
    int n = blockIdx.x;
    int t = n % TSEQ;
    int v = idx[n];
    for (int c = threadIdx.x; c < CDIM; c += blockDim.x)
        x[n * CDIM + c] = tok[v * CDIM + c] + pos[t * CDIM + c];
}

// ======================= layernorm =======================
__global__ void ln_kernel(const float* __restrict__ x,
                          const float* __restrict__ g,
                          const float* __restrict__ b,
                          float* __restrict__ out,
                          fp16* __restrict__ oh) {
    int n = blockIdx.x;
    int tid = threadIdx.x;
    __shared__ float s1[256], s2[256];
    const float* xr = x + (size_t)n * CDIM;
    float a = 0.f, q = 0.f;
    for (int c = tid; c < CDIM; c += 256) { float v = xr[c]; a += v; q += v * v; }
    s1[tid] = a; s2[tid] = q;
    __syncthreads();
    for (int s = 128; s > 0; s >>= 1) {
        if (tid < s) { s1[tid] += s1[tid + s]; s2[tid] += s2[tid + s]; }
        __syncthreads();
    }
    float mean = s1[0] * (1.f / CDIM);
    float var  = s2[0] * (1.f / CDIM) - mean * mean;
    float r = rsqrtf(var + 1e-5f);
    for (int c = tid; c < CDIM; c += 256) {
        float o = (xr[c] - mean) * r * g[c] + b[c];
        size_t p = (size_t)n * CDIM + c;
        out[p] = o;
        oh[p] = __float2half_rn(o);
    }
}

// ======================= attention v2 (z-split, AV unrolled) ================
#define KV_STR 25
#define ATTN_SMEM ((TSEQ * KV_STR * 2 + 8 * 424 + 8 * 24) * 4)

__global__ void __launch_bounds__(256)
attn2_kernel(const float* __restrict__ qkv, fp16* __restrict__ atth) {
    int h = blockIdx.x, b = blockIdx.y, z = blockIdx.z;
    extern __shared__ float sm[];
    float* Ks = sm;
    float* Vs = Ks + TSEQ * KV_STR;
    float* sc = Vs + TSEQ * KV_STR;
    float* qb = sc + 8 * 424;

    int tid = threadIdx.x, wid = tid >> 5, lane = tid & 31;
    int n0 = b * TSEQ;

    for (int i = tid; i < TSEQ * HSD; i += 256) {
        int u = i / HSD, s = i - u * HSD;
        const float* base = qkv + (size_t)(n0 + u) * (3 * CDIM) + h * HSD + s;
        Ks[u * KV_STR + s] = base[CDIM];
        Vs[u * KV_STR + s] = base[2 * CDIM];
    }
    __syncthreads();

    const float scale = 0.20412414523193154f;
    float* scw = sc + wid * 424;
    float* qw  = qb + wid * 24;

    for (int t = z * 8 + wid; t < TSEQ; t += 16) {
        if (lane < HSD)
            qw[lane] = qkv[(size_t)(n0 + t) * (3 * CDIM) + h * HSD + lane];
        __syncwarp();

        float lmax = -1e30f;
        for (int u = lane; u <= t; u += 32) {
            const float* kr = Ks + u * KV_STR;
            float d = 0.f;
#pragma unroll
            for (int s = 0; s < HSD; s++) d += qw[s] * kr[s];
            d *= scale;
            scw[u] = d;
            lmax = fmaxf(lmax, d);
        }
        for (int o = 16; o > 0; o >>= 1)
            lmax = fmaxf(lmax, __shfl_xor_sync(0xFFFFFFFFu, lmax, o));

        float lsum = 0.f;
        for (int u = lane; u <= t; u += 32) {
            float ev = expf(scw[u] - lmax);
            scw[u] = ev;
            lsum += ev;
        }
        for (int o = 16; o > 0; o >>= 1)
            lsum += __shfl_xor_sync(0xFFFFFFFFu, lsum, o);
        float inv = 1.f / lsum;
        __syncwarp();

        if (lane < HSD) {
            float a0 = 0.f, a1 = 0.f, a2 = 0.f, a3 = 0.f;
            int u = 0;
            for (; u + 4 <= t + 1; u += 4) {
                a0 += scw[u + 0] * Vs[(u + 0) * KV_STR + lane];
                a1 += scw[u + 1] * Vs[(u + 1) * KV_STR + lane];
                a2 += scw[u + 2] * Vs[(u + 2) * KV_STR + lane];
                a3 += scw[u + 3] * Vs[(u + 3) * KV_STR + lane];
            }
            for (; u <= t; u++) a0 += scw[u] * Vs[u * KV_STR + lane];
            float a = ((a0 + a1) + (a2 + a3)) * inv;
            atth[(size_t)(n0 + t) * CDIM + h * HSD + lane] = __float2half_rn(a);
        }
        __syncwarp();
    }
}

// ======================= gate softmax v2 =======================
__global__ void __launch_bounds__(256)
gate2_kernel(const float* __restrict__ h2, const float* __restrict__ gwT,
             const float* __restrict__ gb, float* __restrict__ gates) {
    int n = blockIdx.x;
    int tid = threadIdx.x, wid = tid >> 5, lane = tid & 31;
    __shared__ float lg[NE];
    __shared__ float hsm[CDIM];
    for (int c = tid; c < CDIM; c += 256) hsm[c] = h2[(size_t)n * CDIM + c];
    __syncthreads();
    for (int e = wid; e < NE; e += 8) {
        const float* w = gwT + (size_t)e * CDIM;
        float a = 0.f;
        for (int c = lane; c < CDIM; c += 32) a += hsm[c] * w[c];
        for (int o = 16; o > 0; o >>= 1) a += __shfl_xor_sync(0xFFFFFFFFu, a, o);
        if (lane == 0) lg[e] = a + gb[e];
    }
    __syncthreads();
    if (tid < 32) {
        float v = lg[tid];
        float mx = v;
        for (int o = 16; o > 0; o >>= 1) mx = fmaxf(mx, __shfl_xor_sync(0xFFFFFFFFu, mx, o));
        float ex = expf(v - mx);
        float smv = ex;
        for (int o = 16; o > 0; o >>= 1) smv += __shfl_xor_sync(0xFFFFFFFFu, smv, o);
        gates[n * NE + tid] = ex / smv;
    }
}

// ======================= MoE combine (fp16 eo) =======================
__global__ void combine_kernel(const fp16* __restrict__ eo,
                               const float* __restrict__ gates,
                               float* __restrict__ x) {
    int n = blockIdx.x;
    __shared__ float gs[NE];
    if (threadIdx.x < NE) gs[threadIdx.x] = gates[n * NE + threadIdx.x];
    __syncthreads();
    for (int c = threadIdx.x; c < CDIM; c += blockDim.x) {
        float a = 0.f;
        const fp16* er = eo + (size_t)n * (NE * CDIM) + c;
#pragma unroll 8
        for (int e = 0; e < NE; e++) a += gs[e] * __half2float(er[e * CDIM]);
        x[(size_t)n * CDIM + c] += a;
    }
}

// ======================= scalar SGEMM (lm head only) =======================
__global__ void __launch_bounds__(256)
lm_head_kernel(const float* __restrict__ A, const float* __restrict__ B,
               const float* __restrict__ bias, float* __restrict__ C,
               int M, int N, int K) {
    __shared__ float As[64][17];
    __shared__ float Bs[16][64];
    int tid = threadIdx.x;
    int jTile = blockIdx.x * 64;
    int mTile = blockIdx.y * 64;
    int tx = tid & 15, ty = tid >> 4;

    float acc[4][4];
#pragma unroll
    for (int r = 0; r < 4; r++)
#pragma unroll
        for (int c = 0; c < 4; c++) acc[r][c] = 0.f;

    int aRow = tid >> 2, aK = (tid & 3) * 4;
    int bJ = tid & 63, bK0 = tid >> 6;

    for (int k0 = 0; k0 < K; k0 += 16) {
        int m = mTile + aRow;
        if (m < M) {
            float4 av = *(const float4*)(A + (size_t)m * K + k0 + aK);
            As[aRow][aK + 0] = av.x; As[aRow][aK + 1] = av.y;
            As[aRow][aK + 2] = av.z; As[aRow][aK + 3] = av.w;
        } else {
            As[aRow][aK + 0] = 0.f; As[aRow][aK + 1] = 0.f;
            As[aRow][aK + 2] = 0.f; As[aRow][aK + 3] = 0.f;
        }
#pragma unroll
        for (int i = 0; i < 4; i++) {
            int kk = bK0 + i * 4;
            Bs[kk][bJ] = (jTile + bJ < N)
                ? B[(size_t)(k0 + kk) * N + jTile + bJ] : 0.f;
        }
        __syncthreads();
#pragma unroll
        for (int k = 0; k < 16; k++) {
            float4 bv = *(const float4*)&Bs[k][tx * 4];
            float a0 = As[ty * 4 + 0][k], a1 = As[ty * 4 + 1][k];
            float a2 = As[ty * 4 + 2][k], a3 = As[ty * 4 + 3][k];
            acc[0][0] += a0 * bv.x; acc[0][1] += a0 * bv.y; acc[0][2] += a0 * bv.z; acc[0][3] += a0 * bv.w;
            acc[1][0] += a1 * bv.x; acc[1][1] += a1 * bv.y; acc[1][2] += a1 * bv.z; acc[1][3] += a1 * bv.w;
            acc[2][0] += a2 * bv.x; acc[2][1] += a2 * bv.y; acc[2][2] += a2 * bv.z; acc[2][3] += a2 * bv.w;
            acc[3][0] += a3 * bv.x; acc[3][1] += a3 * bv.y; acc[3][2] += a3 * bv.z; acc[3][3] += a3 * bv.w;
        }
        __syncthreads();
    }
#pragma unroll
    for (int r = 0; r < 4; r++) {
        int m = mTile + ty * 4 + r;
        if (m >= M) continue;
#pragma unroll
        for (int c = 0; c < 4; c++) {
            int j = jTile + tx * 4 + c;
            if (j >= N) continue;
            C[(size_t)m * N + j] = acc[r][c] + bias[j];
        }
    }
}

// ======================= launch =======================
extern "C" void kernel_launch(void* const* d_in, const int* in_sizes, int n_in,
                              void* d_out, int out_size) {
    const int*   idx    = (const int*)  d_in[0];
    const float* tok    = (const float*)d_in[1];
    const float* pos    = (const float*)d_in[2];
    const float* ln1_g  = (const float*)d_in[3];
    const float* ln1_b  = (const float*)d_in[4];
    const float* Wq     = (const float*)d_in[5];
    const float* Wk     = (const float*)d_in[6];
    const float* Wv     = (const float*)d_in[7];
    const float* Wo     = (const float*)d_in[8];
    const float* bo     = (const float*)d_in[9];
    const float* ln2_g  = (const float*)d_in[10];
    const float* ln2_b  = (const float*)d_in[11];
    const float* gate_w = (const float*)d_in[12];
    const float* gate_b = (const float*)d_in[13];
    const float* W1     = (const float*)d_in[14];
    const float* b1     = (const float*)d_in[15];
    const float* W2     = (const float*)d_in[16];
    const float* b2     = (const float*)d_in[17];
    const float* lnf_g  = (const float*)d_in[18];
    const float* lnf_b  = (const float*)d_in[19];
    const float* lm_w   = (const float*)d_in[20];
    const float* lm_b   = (const float*)d_in[21];
    float* out = (float*)d_out;

    float *x, *h, *qkv, *gates, *gwT;
    fp16 *eo, *hh, *atth, *wpth, *wptl, *woth, *wotl;
    fp16 *w1th, *w2th, *hidh;
    cudaGetSymbolAddress((void**)&x,     g_x);
    cudaGetSymbolAddress((void**)&h,     g_h);
    cudaGetSymbolAddress((void**)&qkv,   g_qkv);
    cudaGetSymbolAddress((void**)&gates, g_gates);
    cudaGetSymbolAddress((void**)&gwT,   g_gwT);
    cudaGetSymbolAddress((void**)&eo,    g_eo);
    cudaGetSymbolAddress((void**)&hh,    g_hh);
    cudaGetSymbolAddress((void**)&atth,  g_atth);
    cudaGetSymbolAddress((void**)&wpth,  g_wpth);
    cudaGetSymbolAddress((void**)&wptl,  g_wptl);
    cudaGetSymbolAddress((void**)&woth,  g_woth);
    cudaGetSymbolAddress((void**)&wotl,  g_wotl);
    cudaGetSymbolAddress((void**)&w1th,  g_w1th);
    cudaGetSymbolAddress((void**)&w2th,  g_w2th);
    cudaGetSymbolAddress((void**)&hidh,  g_hidh);

    cudaFuncSetAttribute(mma_gemmA<0>, cudaFuncAttributeMaxDynamicSharedMemorySize, SMEM_3PL);
    cudaFuncSetAttribute(mma_gemmA<2>, cudaFuncAttributeMaxDynamicSharedMemorySize, SMEM_3PL);
    cudaFuncSetAttribute(mma_gemm64<3>, cudaFuncAttributeMaxDynamicSharedMemorySize, SMEM_2PL);
    cudaFuncSetAttribute(mma_gemm64<4>, cudaFuncAttributeMaxDynamicSharedMemorySize, SMEM_2PL);
    cudaFuncSetAttribute(attn2_kernel, cudaFuncAttributeMaxDynamicSharedMemorySize, ATTN_SMEM);

    const int MT = (NTOK + 127) / 128;   // 7

    // ---- pre-convert weights ----
    for (int l = 0; l < NL; l++) {
        convT<0><<<dim3(CDIM / 64, F4D / 64, NE), 256>>>(
            W1 + (size_t)l * NE * CDIM * F4D, (long long)CDIM * F4D, CDIM, F4D,
            w1th + (size_t)l * NE * F4D * CDIM, nullptr,
            (long long)F4D * CDIM);
        convT<0><<<dim3(F4D / 64, CDIM / 64, NE), 256>>>(
            W2 + (size_t)l * NE * F4D * CDIM, (long long)F4D * CDIM, F4D, CDIM,
            w2th + (size_t)l * NE * CDIM * F4D, nullptr,
            (long long)CDIM * F4D);
        convT<1><<<dim3(CDIM / 64, CDIM / 64, 1), 256>>>(
            Wo + (size_t)l * CDIM * CDIM, 0, CDIM, CDIM,
            woth + (size_t)l * CDIM * CDIM, wotl + (size_t)l * CDIM * CDIM, 0);
    }

    embed_kernel<<<NTOK, 256>>>(idx, tok, pos, x);

    for (int l = 0; l < NL; l++) {
        // --- attention ---
        ln_kernel<<<NTOK, 256>>>(x, ln1_g + l * CDIM, ln1_b + l * CDIM, h, hh);
        pack_qkvT2<<<dim3(NH, 3), 256>>>(
            Wq + (size_t)l * NH * CDIM * HSD,
            Wk + (size_t)l * NH * CDIM * HSD,
            Wv + (size_t)l * NH * CDIM * HSD, wpth, wptl);
        mma_gemmA<0><<<dim3(MT * 18), 256, SMEM_3PL>>>(
            hh, CDIM, wpth, wptl, CDIM, nullptr,
            qkv, 3 * CDIM, NTOK, MT, CDIM / 64);
        attn2_kernel<<<dim3(NH, BSZ, 2), 256, ATTN_SMEM>>>(qkv, atth);
        mma_gemmA<2><<<dim3(MT * 6), 256, SMEM_3PL>>>(
            atth, CDIM,
            woth + (size_t)l * CDIM * CDIM, wotl + (size_t)l * CDIM * CDIM, CDIM,
            bo + l * CDIM, x, CDIM, NTOK, MT, CDIM / 64);

        // --- MoE ---
        ln_kernel<<<NTOK, 256>>>(x, ln2_g + l * CDIM, ln2_b + l * CDIM, h, hh);
        gwT_kernel<<<(NE * CDIM + 255) / 256, 256>>>(
            gate_w + (size_t)l * CDIM * NE, gwT);
        gate2_kernel<<<NTOK, 256>>>(h, gwT, gate_b + l * NE, gates);
        mma_gemm64<3><<<dim3(MT * (F4D / 128), NE), 256, SMEM_2PL>>>(
            hh, CDIM, 0,
            w1th + (size_t)l * NE * F4D * CDIM, CDIM, (long long)F4D * CDIM,
            b1 + (size_t)l * NE * F4D, F4D,
            hidh, (long long)NE * F4D, F4D,
            NTOK, MT, CDIM / 64);
        mma_gemm64<4><<<dim3(MT * (CDIM / 128), NE), 256, SMEM_2PL>>>(
            hidh, (long long)NE * F4D, F4D,
            w2th + (size_t)l * NE * CDIM * F4D, F4D, (long long)CDIM * F4D,
            b2 + (size_t)l * NE * CDIM, CDIM,
            eo, (long long)NE * CDIM, CDIM,
            NTOK, MT, F4D / 64);
        combine_kernel<<<NTOK, 256>>>(eo, gates, x);
    }

    // --- final LN + lm head ---
    ln_kernel<<<NTOK, 256>>>(x, lnf_g, lnf_b, h, hh);
    lm_head_kernel<<<dim3((NV + 63) / 64, (NTOK + 63) / 64), 256>>>(
        h, lm_w, lm_b, out, NTOK, NV, CDIM);
}